// round 1
// baseline (speedup 1.0000x reference)
#include <cuda_runtime.h>

#define NB 4
#define NT 4096
#define NC 1024
#define NH 64
#define NROWS (NB * NT)

// Scratch for projected q/k/v: [B*T, H] each (4 MB each, L2-resident).
__device__ float g_q[NROWS * NH];
__device__ float g_k[NROWS * NH];
__device__ float g_v[NROWS * NH];

// ---------------------------------------------------------------------------
// Kernel 1: fused QKV projection.
//   q/k/v[row, h] = sum_c x[row, c] * W{q,k,v}[c, h]
// Grid: 128 blocks (128 rows each). Block: 256 threads.
// Smem: Xs[64][128] (transposed chunk, c-major) + Ws[64][196] (q|k|v cols, padded)
// Thread micro-tile: 8 rows x 12 cols  (16 row-groups x 16 col-groups)
// ---------------------------------------------------------------------------
__global__ __launch_bounds__(256, 1)
void qkv_kernel(const float* __restrict__ x, const float* __restrict__ Wq,
                const float* __restrict__ Wk, const float* __restrict__ Wv)
{
    extern __shared__ float sm[];
    float* Xs = sm;              // [64][128]  (c, row)
    float* Ws = sm + 64 * 128;   // [64][196]  (c, col) cols: q:0-63 k:64-127 v:128-191

    const int t    = threadIdx.x;
    const int hg   = t & 15;     // col-group (12 cols)
    const int rg   = t >> 4;     // row-group (8 rows)
    const int r0   = rg * 8;
    const int row0 = blockIdx.x * 128;

    float acc[8][12];
#pragma unroll
    for (int i = 0; i < 8; ++i)
#pragma unroll
        for (int j = 0; j < 12; ++j) acc[i][j] = 0.f;

    for (int c0 = 0; c0 < NC; c0 += 64) {
        // Load X chunk transposed into smem (conflict-free STS; scattered global
        // reads are fine: small volume, wide HBM/L2).
#pragma unroll
        for (int it = 0; it < 8; ++it) {
            int i   = t + it * 256;   // 0..2047 float4s
            int c4  = (i >> 7) * 4;   // 0,4,...,60
            int row = i & 127;
            float4 xv = *reinterpret_cast<const float4*>(
                x + (row0 + row) * NC + c0 + c4);
            Xs[(c4 + 0) * 128 + row] = xv.x;
            Xs[(c4 + 1) * 128 + row] = xv.y;
            Xs[(c4 + 2) * 128 + row] = xv.z;
            Xs[(c4 + 3) * 128 + row] = xv.w;
        }
        // Load W chunks (coalesced, STS.128)
#pragma unroll
        for (int it = 0; it < 4; ++it) {
            int i  = t + it * 256;    // 0..1023
            int cc = i >> 4;
            int h4 = (i & 15) * 4;
            float4 a = *reinterpret_cast<const float4*>(Wq + (c0 + cc) * NH + h4);
            float4 b = *reinterpret_cast<const float4*>(Wk + (c0 + cc) * NH + h4);
            float4 c = *reinterpret_cast<const float4*>(Wv + (c0 + cc) * NH + h4);
            *reinterpret_cast<float4*>(Ws + cc * 196 +       h4) = a;
            *reinterpret_cast<float4*>(Ws + cc * 196 +  64 + h4) = b;
            *reinterpret_cast<float4*>(Ws + cc * 196 + 128 + h4) = c;
        }
        __syncthreads();

#pragma unroll 4
        for (int cc = 0; cc < 64; ++cc) {
            float4 xa = *reinterpret_cast<const float4*>(Xs + cc * 128 + r0);
            float4 xb = *reinterpret_cast<const float4*>(Xs + cc * 128 + r0 + 4);
            float4 w0 = *reinterpret_cast<const float4*>(Ws + cc * 196 + hg * 12);
            float4 w1 = *reinterpret_cast<const float4*>(Ws + cc * 196 + hg * 12 + 4);
            float4 w2 = *reinterpret_cast<const float4*>(Ws + cc * 196 + hg * 12 + 8);
            float xs[8]  = {xa.x, xa.y, xa.z, xa.w, xb.x, xb.y, xb.z, xb.w};
            float ws[12] = {w0.x, w0.y, w0.z, w0.w, w1.x, w1.y, w1.z, w1.w,
                            w2.x, w2.y, w2.z, w2.w};
#pragma unroll
            for (int i = 0; i < 8; ++i)
#pragma unroll
                for (int j = 0; j < 12; ++j)
                    acc[i][j] = fmaf(xs[i], ws[j], acc[i][j]);
        }
        __syncthreads();
    }

#pragma unroll
    for (int i = 0; i < 8; ++i) {
        int row = row0 + r0 + i;
#pragma unroll
        for (int j4 = 0; j4 < 3; ++j4) {
            int col = hg * 12 + j4 * 4;   // multiple of 4, never crosses a 64-boundary
            float4 v = make_float4(acc[i][j4 * 4 + 0], acc[i][j4 * 4 + 1],
                                   acc[i][j4 * 4 + 2], acc[i][j4 * 4 + 3]);
            float* dst;
            if (col < 64)        dst = g_q + row * NH + col;
            else if (col < 128)  dst = g_k + row * NH + (col - 64);
            else                 dst = g_v + row * NH + (col - 128);
            *reinterpret_cast<float4*>(dst) = v;
        }
    }
}

// ---------------------------------------------------------------------------
// Kernel 2: causal flash attention, fp32, NO 1/sqrt(d) scaling.
// Tiles: Mq = Mk = 64. Block = 256 threads; thread micro-tile 4x4.
// Each block processes q-tile pair (x, 63-x): (x+1) + (64-x) = 65 key-block
// iterations per block -> perfectly balanced, 128 blocks = 1 wave.
// Smem: Qt/Kt[64][68] transposed (h, idx), Vs[64][68] (krow, h), Pt[64][68] (kcol, qrow)
// ---------------------------------------------------------------------------
__global__ __launch_bounds__(256, 1)
void attn_kernel(float* __restrict__ out)
{
    extern __shared__ float sm[];
    float* Qt = sm;               // [64][68]
    float* Kt = Qt + 64 * 68;     // [64][68]
    float* Vs = Kt + 64 * 68;     // [64][68]
    float* Pt = Vs + 64 * 68;     // [64][68]

    const int t    = threadIdx.x;
    const int cg   = t & 15;
    const int rg   = t >> 4;
    const int c0   = cg * 4;
    const int r0   = rg * 4;
    const int xblk = blockIdx.x;  // 0..31
    const int b    = blockIdx.y;
    const int base = b * NT;

    for (int rep = 0; rep < 2; ++rep) {
        const int qb = rep ? (63 - xblk) : xblk;
        const int q0 = qb * 64;

        __syncthreads();
        // Load Q tile transposed: Qt[h][row]
#pragma unroll
        for (int it = 0; it < 4; ++it) {
            int i   = t + it * 256;   // 0..1023
            int h4  = (i >> 6) * 4;
            int row = i & 63;
            float4 qv = *reinterpret_cast<const float4*>(
                g_q + (base + q0 + row) * NH + h4);
            Qt[(h4 + 0) * 68 + row] = qv.x;
            Qt[(h4 + 1) * 68 + row] = qv.y;
            Qt[(h4 + 2) * 68 + row] = qv.z;
            Qt[(h4 + 3) * 68 + row] = qv.w;
        }

        float o[4][4], m[4], l[4];
#pragma unroll
        for (int i = 0; i < 4; ++i) {
            m[i] = -1e30f; l[i] = 0.f;
#pragma unroll
            for (int j = 0; j < 4; ++j) o[i][j] = 0.f;
        }

        for (int kb = 0; kb <= qb; ++kb) {
            __syncthreads();   // previous iteration's PV reads done
            // Load K transposed (Kt[h][col]) and V natural (Vs[krow][h])
#pragma unroll
            for (int it = 0; it < 4; ++it) {
                int i   = t + it * 256;
                int h4  = (i >> 6) * 4;
                int row = i & 63;
                float4 kv = *reinterpret_cast<const float4*>(
                    g_k + (base + kb * 64 + row) * NH + h4);
                Kt[(h4 + 0) * 68 + row] = kv.x;
                Kt[(h4 + 1) * 68 + row] = kv.y;
                Kt[(h4 + 2) * 68 + row] = kv.z;
                Kt[(h4 + 3) * 68 + row] = kv.w;
                float4 vv = *reinterpret_cast<const float4*>(
                    g_v + (base + kb * 64 + row) * NH + h4);
                *reinterpret_cast<float4*>(Vs + row * 68 + h4) = vv;
            }
            __syncthreads();

            // S = Q K^T  (4x4 outer-product micro-tile)
            float s[4][4];
#pragma unroll
            for (int i = 0; i < 4; ++i)
#pragma unroll
                for (int j = 0; j < 4; ++j) s[i][j] = 0.f;

#pragma unroll 8
            for (int h = 0; h < 64; ++h) {
                float4 qa = *reinterpret_cast<const float4*>(Qt + h * 68 + r0);
                float4 ka = *reinterpret_cast<const float4*>(Kt + h * 68 + c0);
                float qr[4] = {qa.x, qa.y, qa.z, qa.w};
                float kr[4] = {ka.x, ka.y, ka.z, ka.w};
#pragma unroll
                for (int i = 0; i < 4; ++i)
#pragma unroll
                    for (int j = 0; j < 4; ++j)
                        s[i][j] = fmaf(qr[i], kr[j], s[i][j]);
            }

            // Causal mask: only the diagonal tile needs it (kb < qb fully valid)
            if (kb == qb) {
#pragma unroll
                for (int i = 0; i < 4; ++i)
#pragma unroll
                    for (int j = 0; j < 4; ++j)
                        if (c0 + j > r0 + i) s[i][j] = -1e30f;
            }

            // Online softmax (row stats reduced across the 16-lane cg group)
#pragma unroll
            for (int i = 0; i < 4; ++i) {
                float rmax = fmaxf(fmaxf(s[i][0], s[i][1]), fmaxf(s[i][2], s[i][3]));
#pragma unroll
                for (int off = 8; off >= 1; off >>= 1)
                    rmax = fmaxf(rmax, __shfl_xor_sync(0xffffffffu, rmax, off));
                float mn   = fmaxf(m[i], rmax);
                float corr = __expf(m[i] - mn);
                float rs = 0.f;
#pragma unroll
                for (int j = 0; j < 4; ++j) {
                    s[i][j] = __expf(s[i][j] - mn);
                    rs += s[i][j];
                }
#pragma unroll
                for (int off = 8; off >= 1; off >>= 1)
                    rs += __shfl_xor_sync(0xffffffffu, rs, off);
                l[i] = l[i] * corr + rs;
                m[i] = mn;
#pragma unroll
                for (int j = 0; j < 4; ++j) o[i][j] *= corr;
            }

            // Store P transposed: Pt[kcol][qrow]
#pragma unroll
            for (int j = 0; j < 4; ++j)
                *reinterpret_cast<float4*>(Pt + (c0 + j) * 68 + r0) =
                    make_float4(s[0][j], s[1][j], s[2][j], s[3][j]);
            __syncthreads();

            // O += P V  (4x4 outer-product; o columns are H dims c0..c0+3)
#pragma unroll 8
            for (int kk = 0; kk < 64; ++kk) {
                float4 pa = *reinterpret_cast<const float4*>(Pt + kk * 68 + r0);
                float4 va = *reinterpret_cast<const float4*>(Vs + kk * 68 + c0);
                float pr[4] = {pa.x, pa.y, pa.z, pa.w};
                float vr[4] = {va.x, va.y, va.z, va.w};
#pragma unroll
                for (int i = 0; i < 4; ++i)
#pragma unroll
                    for (int j = 0; j < 4; ++j)
                        o[i][j] = fmaf(pr[i], vr[j], o[i][j]);
            }
        }

        // Epilogue: normalize and write out[b, q0+r, h]
#pragma unroll
        for (int i = 0; i < 4; ++i) {
            float inv = 1.f / l[i];
            float4 v = make_float4(o[i][0] * inv, o[i][1] * inv,
                                   o[i][2] * inv, o[i][3] * inv);
            *reinterpret_cast<float4*>(
                out + (size_t)(base + q0 + r0 + i) * NH + c0) = v;
        }
    }
}

// ---------------------------------------------------------------------------
extern "C" void kernel_launch(void* const* d_in, const int* in_sizes, int n_in,
                              void* d_out, int out_size)
{
    (void)in_sizes; (void)n_in; (void)out_size;
    const float* x  = (const float*)d_in[0];
    const float* Wq = (const float*)d_in[1];
    const float* Wk = (const float*)d_in[2];
    const float* Wv = (const float*)d_in[3];
    float* out = (float*)d_out;

    const int smem1 = (64 * 128 + 64 * 196) * 4;  // 82944 B
    const int smem2 = (4 * 64 * 68) * 4;          // 69632 B
    cudaFuncSetAttribute(qkv_kernel, cudaFuncAttributeMaxDynamicSharedMemorySize, smem1);
    cudaFuncSetAttribute(attn_kernel, cudaFuncAttributeMaxDynamicSharedMemorySize, smem2);

    qkv_kernel<<<128, 256, smem1>>>(x, Wq, Wk, Wv);
    attn_kernel<<<dim3(32, NB), 256, smem2>>>(out);
}

// round 2
// speedup vs baseline: 1.0009x; 1.0009x over previous
#include <cuda_runtime.h>

#define NB 4
#define NT 4096
#define NC 1024
#define NH 64
#define NROWS (NB * NT)

// Scratch for projected q/k/v: [B*T, H] each (4 MB each, L2-resident).
__device__ float g_q[NROWS * NH];
__device__ float g_k[NROWS * NH];
__device__ float g_v[NROWS * NH];

// ---------------------------------------------------------------------------
// Kernel 1: fused QKV projection.
//   q/k/v[row, h] = sum_c x[row, c] * W{q,k,v}[c, h]
// Grid: 128 blocks (128 rows each). Block: 256 threads.
// Smem: Xs[64][128] (transposed chunk, c-major) + Ws[64][196] (q|k|v cols, padded)
// Thread micro-tile: 8 rows x 12 cols  (16 row-groups x 16 col-groups)
// ---------------------------------------------------------------------------
__global__ __launch_bounds__(256, 1)
void qkv_kernel(const float* __restrict__ x, const float* __restrict__ Wq,
                const float* __restrict__ Wk, const float* __restrict__ Wv)
{
    extern __shared__ float sm[];
    float* Xs = sm;              // [64][128]  (c, row)
    float* Ws = sm + 64 * 128;   // [64][196]  (c, col) cols: q:0-63 k:64-127 v:128-191

    const int t    = threadIdx.x;
    const int hg   = t & 15;     // col-group (12 cols)
    const int rg   = t >> 4;     // row-group (8 rows)
    const int r0   = rg * 8;
    const int row0 = blockIdx.x * 128;

    float acc[8][12];
#pragma unroll
    for (int i = 0; i < 8; ++i)
#pragma unroll
        for (int j = 0; j < 12; ++j) acc[i][j] = 0.f;

    for (int c0 = 0; c0 < NC; c0 += 64) {
        // Load X chunk transposed into smem (conflict-free STS; scattered global
        // reads are fine: small volume, wide HBM/L2).
#pragma unroll
        for (int it = 0; it < 8; ++it) {
            int i   = t + it * 256;   // 0..2047 float4s
            int c4  = (i >> 7) * 4;   // 0,4,...,60
            int row = i & 127;
            float4 xv = *reinterpret_cast<const float4*>(
                x + (row0 + row) * NC + c0 + c4);
            Xs[(c4 + 0) * 128 + row] = xv.x;
            Xs[(c4 + 1) * 128 + row] = xv.y;
            Xs[(c4 + 2) * 128 + row] = xv.z;
            Xs[(c4 + 3) * 128 + row] = xv.w;
        }
        // Load W chunks (coalesced, STS.128)
#pragma unroll
        for (int it = 0; it < 4; ++it) {
            int i  = t + it * 256;    // 0..1023
            int cc = i >> 4;
            int h4 = (i & 15) * 4;
            float4 a = *reinterpret_cast<const float4*>(Wq + (c0 + cc) * NH + h4);
            float4 b = *reinterpret_cast<const float4*>(Wk + (c0 + cc) * NH + h4);
            float4 c = *reinterpret_cast<const float4*>(Wv + (c0 + cc) * NH + h4);
            *reinterpret_cast<float4*>(Ws + cc * 196 +       h4) = a;
            *reinterpret_cast<float4*>(Ws + cc * 196 +  64 + h4) = b;
            *reinterpret_cast<float4*>(Ws + cc * 196 + 128 + h4) = c;
        }
        __syncthreads();

#pragma unroll 4
        for (int cc = 0; cc < 64; ++cc) {
            float4 xa = *reinterpret_cast<const float4*>(Xs + cc * 128 + r0);
            float4 xb = *reinterpret_cast<const float4*>(Xs + cc * 128 + r0 + 4);
            float4 w0 = *reinterpret_cast<const float4*>(Ws + cc * 196 + hg * 12);
            float4 w1 = *reinterpret_cast<const float4*>(Ws + cc * 196 + hg * 12 + 4);
            float4 w2 = *reinterpret_cast<const float4*>(Ws + cc * 196 + hg * 12 + 8);
            float xs[8]  = {xa.x, xa.y, xa.z, xa.w, xb.x, xb.y, xb.z, xb.w};
            float ws[12] = {w0.x, w0.y, w0.z, w0.w, w1.x, w1.y, w1.z, w1.w,
                            w2.x, w2.y, w2.z, w2.w};
#pragma unroll
            for (int i = 0; i < 8; ++i)
#pragma unroll
                for (int j = 0; j < 12; ++j)
                    acc[i][j] = fmaf(xs[i], ws[j], acc[i][j]);
        }
        __syncthreads();
    }

#pragma unroll
    for (int i = 0; i < 8; ++i) {
        int row = row0 + r0 + i;
#pragma unroll
        for (int j4 = 0; j4 < 3; ++j4) {
            int col = hg * 12 + j4 * 4;   // multiple of 4, never crosses a 64-boundary
            float4 v = make_float4(acc[i][j4 * 4 + 0], acc[i][j4 * 4 + 1],
                                   acc[i][j4 * 4 + 2], acc[i][j4 * 4 + 3]);
            float* dst;
            if (col < 64)        dst = g_q + row * NH + col;
            else if (col < 128)  dst = g_k + row * NH + (col - 64);
            else                 dst = g_v + row * NH + (col - 128);
            *reinterpret_cast<float4*>(dst) = v;
        }
    }
}

// ---------------------------------------------------------------------------
// Kernel 2: causal flash attention, fp32, NO 1/sqrt(d) scaling.
// Tiles: Mq = Mk = 64. Block = 256 threads; thread micro-tile 4x4.
// Each block processes q-tile pair (x, 63-x): (x+1) + (64-x) = 65 key-block
// iterations per block -> perfectly balanced, 128 blocks = 1 wave.
// Smem: Qt/Kt[64][68] transposed (h, idx), Vs[64][68] (krow, h), Pt[64][68] (kcol, qrow)
// ---------------------------------------------------------------------------
__global__ __launch_bounds__(256, 1)
void attn_kernel(float* __restrict__ out)
{
    extern __shared__ float sm[];
    float* Qt = sm;               // [64][68]
    float* Kt = Qt + 64 * 68;     // [64][68]
    float* Vs = Kt + 64 * 68;     // [64][68]
    float* Pt = Vs + 64 * 68;     // [64][68]

    const int t    = threadIdx.x;
    const int cg   = t & 15;
    const int rg   = t >> 4;
    const int c0   = cg * 4;
    const int r0   = rg * 4;
    const int xblk = blockIdx.x;  // 0..31
    const int b    = blockIdx.y;
    const int base = b * NT;

    for (int rep = 0; rep < 2; ++rep) {
        const int qb = rep ? (63 - xblk) : xblk;
        const int q0 = qb * 64;

        __syncthreads();
        // Load Q tile transposed: Qt[h][row]
#pragma unroll
        for (int it = 0; it < 4; ++it) {
            int i   = t + it * 256;   // 0..1023
            int h4  = (i >> 6) * 4;
            int row = i & 63;
            float4 qv = *reinterpret_cast<const float4*>(
                g_q + (base + q0 + row) * NH + h4);
            Qt[(h4 + 0) * 68 + row] = qv.x;
            Qt[(h4 + 1) * 68 + row] = qv.y;
            Qt[(h4 + 2) * 68 + row] = qv.z;
            Qt[(h4 + 3) * 68 + row] = qv.w;
        }

        float o[4][4], m[4], l[4];
#pragma unroll
        for (int i = 0; i < 4; ++i) {
            m[i] = -1e30f; l[i] = 0.f;
#pragma unroll
            for (int j = 0; j < 4; ++j) o[i][j] = 0.f;
        }

        for (int kb = 0; kb <= qb; ++kb) {
            __syncthreads();   // previous iteration's PV reads done
            // Load K transposed (Kt[h][col]) and V natural (Vs[krow][h])
#pragma unroll
            for (int it = 0; it < 4; ++it) {
                int i   = t + it * 256;
                int h4  = (i >> 6) * 4;
                int row = i & 63;
                float4 kv = *reinterpret_cast<const float4*>(
                    g_k + (base + kb * 64 + row) * NH + h4);
                Kt[(h4 + 0) * 68 + row] = kv.x;
                Kt[(h4 + 1) * 68 + row] = kv.y;
                Kt[(h4 + 2) * 68 + row] = kv.z;
                Kt[(h4 + 3) * 68 + row] = kv.w;
                float4 vv = *reinterpret_cast<const float4*>(
                    g_v + (base + kb * 64 + row) * NH + h4);
                *reinterpret_cast<float4*>(Vs + row * 68 + h4) = vv;
            }
            __syncthreads();

            // S = Q K^T  (4x4 outer-product micro-tile)
            float s[4][4];
#pragma unroll
            for (int i = 0; i < 4; ++i)
#pragma unroll
                for (int j = 0; j < 4; ++j) s[i][j] = 0.f;

#pragma unroll 8
            for (int h = 0; h < 64; ++h) {
                float4 qa = *reinterpret_cast<const float4*>(Qt + h * 68 + r0);
                float4 ka = *reinterpret_cast<const float4*>(Kt + h * 68 + c0);
                float qr[4] = {qa.x, qa.y, qa.z, qa.w};
                float kr[4] = {ka.x, ka.y, ka.z, ka.w};
#pragma unroll
                for (int i = 0; i < 4; ++i)
#pragma unroll
                    for (int j = 0; j < 4; ++j)
                        s[i][j] = fmaf(qr[i], kr[j], s[i][j]);
            }

            // Causal mask: only the diagonal tile needs it (kb < qb fully valid)
            if (kb == qb) {
#pragma unroll
                for (int i = 0; i < 4; ++i)
#pragma unroll
                    for (int j = 0; j < 4; ++j)
                        if (c0 + j > r0 + i) s[i][j] = -1e30f;
            }

            // Online softmax (row stats reduced across the 16-lane cg group)
#pragma unroll
            for (int i = 0; i < 4; ++i) {
                float rmax = fmaxf(fmaxf(s[i][0], s[i][1]), fmaxf(s[i][2], s[i][3]));
#pragma unroll
                for (int off = 8; off >= 1; off >>= 1)
                    rmax = fmaxf(rmax, __shfl_xor_sync(0xffffffffu, rmax, off));
                float mn   = fmaxf(m[i], rmax);
                float corr = __expf(m[i] - mn);
                float rs = 0.f;
#pragma unroll
                for (int j = 0; j < 4; ++j) {
                    s[i][j] = __expf(s[i][j] - mn);
                    rs += s[i][j];
                }
#pragma unroll
                for (int off = 8; off >= 1; off >>= 1)
                    rs += __shfl_xor_sync(0xffffffffu, rs, off);
                l[i] = l[i] * corr + rs;
                m[i] = mn;
#pragma unroll
                for (int j = 0; j < 4; ++j) o[i][j] *= corr;
            }

            // Store P transposed: Pt[kcol][qrow]
#pragma unroll
            for (int j = 0; j < 4; ++j)
                *reinterpret_cast<float4*>(Pt + (c0 + j) * 68 + r0) =
                    make_float4(s[0][j], s[1][j], s[2][j], s[3][j]);
            __syncthreads();

            // O += P V  (4x4 outer-product; o columns are H dims c0..c0+3)
#pragma unroll 8
            for (int kk = 0; kk < 64; ++kk) {
                float4 pa = *reinterpret_cast<const float4*>(Pt + kk * 68 + r0);
                float4 va = *reinterpret_cast<const float4*>(Vs + kk * 68 + c0);
                float pr[4] = {pa.x, pa.y, pa.z, pa.w};
                float vr[4] = {va.x, va.y, va.z, va.w};
#pragma unroll
                for (int i = 0; i < 4; ++i)
#pragma unroll
                    for (int j = 0; j < 4; ++j)
                        o[i][j] = fmaf(pr[i], vr[j], o[i][j]);
            }
        }

        // Epilogue: normalize and write out[b, q0+r, h]
#pragma unroll
        for (int i = 0; i < 4; ++i) {
            float inv = 1.f / l[i];
            float4 v = make_float4(o[i][0] * inv, o[i][1] * inv,
                                   o[i][2] * inv, o[i][3] * inv);
            *reinterpret_cast<float4*>(
                out + (size_t)(base + q0 + r0 + i) * NH + c0) = v;
        }
    }
}

// ---------------------------------------------------------------------------
extern "C" void kernel_launch(void* const* d_in, const int* in_sizes, int n_in,
                              void* d_out, int out_size)
{
    (void)in_sizes; (void)n_in; (void)out_size;
    const float* x  = (const float*)d_in[0];
    const float* Wq = (const float*)d_in[1];
    const float* Wk = (const float*)d_in[2];
    const float* Wv = (const float*)d_in[3];
    float* out = (float*)d_out;

    const int smem1 = (64 * 128 + 64 * 196) * 4;  // 82944 B
    const int smem2 = (4 * 64 * 68) * 4;          // 69632 B
    cudaFuncSetAttribute(qkv_kernel, cudaFuncAttributeMaxDynamicSharedMemorySize, smem1);
    cudaFuncSetAttribute(attn_kernel, cudaFuncAttributeMaxDynamicSharedMemorySize, smem2);

    qkv_kernel<<<128, 256, smem1>>>(x, Wq, Wk, Wv);
    attn_kernel<<<dim3(32, NB), 256, smem2>>>(out);
}

// round 4
// speedup vs baseline: 1.5281x; 1.5268x over previous
#include <cuda_runtime.h>
#include <cuda_bf16.h>
#include <cstdint>

#define NB 4
#define NT 4096
#define NC 1024
#define NH 64
#define NROWS (NB * NT)

// bf16 hi/lo split copies of q, k (row-major [row][h]) and v transposed
// ([b][h][t]) produced by the projection kernel.
__device__ __nv_bfloat16 g_qhi[NROWS * NH];
__device__ __nv_bfloat16 g_qlo[NROWS * NH];
__device__ __nv_bfloat16 g_khi[NROWS * NH];
__device__ __nv_bfloat16 g_klo[NROWS * NH];
__device__ __nv_bfloat16 g_vthi[NB * NH * NT];
__device__ __nv_bfloat16 g_vtlo[NB * NH * NT];

// ===========================================================================
// Helpers (sm_80-era: ldmatrix + mma.sync — valid in plain compute_100 PTX)
// ===========================================================================
__device__ __forceinline__ uint32_t smem_u32(const void* p) {
    uint32_t a;
    asm("{ .reg .u64 t; cvta.to.shared.u64 t, %1; cvt.u32.u64 %0, t; }"
        : "=r"(a) : "l"(p));
    return a;
}
__device__ __forceinline__ void ldsm_x4(uint32_t* r, uint32_t addr) {
    asm volatile("ldmatrix.sync.aligned.m8n8.x4.shared.b16 {%0,%1,%2,%3}, [%4];"
                 : "=r"(r[0]), "=r"(r[1]), "=r"(r[2]), "=r"(r[3]) : "r"(addr));
}
// D(16x8,f32) += A(16x16,bf16) * B(16x8,bf16)   [row.col]
__device__ __forceinline__ void mma_bf16(float* c, const uint32_t* a,
                                         uint32_t b0, uint32_t b1) {
    asm volatile(
        "mma.sync.aligned.m16n8k16.row.col.f32.bf16.bf16.f32 "
        "{%0,%1,%2,%3}, {%4,%5,%6,%7}, {%8,%9}, {%0,%1,%2,%3};"
        : "+f"(c[0]), "+f"(c[1]), "+f"(c[2]), "+f"(c[3])
        : "r"(a[0]), "r"(a[1]), "r"(a[2]), "r"(a[3]), "r"(b0), "r"(b1));
}
__device__ __forceinline__ uint32_t pack_bf16x2(float lo, float hi) {
    uint32_t r;
    asm("cvt.rn.bf16x2.f32 %0, %1, %2;" : "=r"(r) : "f"(hi), "f"(lo));
    return r;
}

// ===========================================================================
// Kernel 1: fused QKV projection (fp32 FFMA), emits bf16 hi/lo splits.
// ===========================================================================
__global__ __launch_bounds__(256, 1)
void qkv_kernel(const float* __restrict__ x, const float* __restrict__ Wq,
                const float* __restrict__ Wk, const float* __restrict__ Wv)
{
    extern __shared__ float sm[];
    float* Xs = sm;              // [64][128]
    float* Ws = sm + 64 * 128;   // [64][196]

    const int t    = threadIdx.x;
    const int hg   = t & 15;
    const int rg   = t >> 4;
    const int r0   = rg * 8;
    const int row0 = blockIdx.x * 128;

    float acc[8][12];
#pragma unroll
    for (int i = 0; i < 8; ++i)
#pragma unroll
        for (int j = 0; j < 12; ++j) acc[i][j] = 0.f;

    for (int c0 = 0; c0 < NC; c0 += 64) {
#pragma unroll
        for (int it = 0; it < 8; ++it) {
            int i   = t + it * 256;
            int c4  = (i >> 7) * 4;
            int row = i & 127;
            float4 xv = *reinterpret_cast<const float4*>(x + (row0 + row) * NC + c0 + c4);
            Xs[(c4 + 0) * 128 + row] = xv.x;
            Xs[(c4 + 1) * 128 + row] = xv.y;
            Xs[(c4 + 2) * 128 + row] = xv.z;
            Xs[(c4 + 3) * 128 + row] = xv.w;
        }
#pragma unroll
        for (int it = 0; it < 4; ++it) {
            int i  = t + it * 256;
            int cc = i >> 4;
            int h4 = (i & 15) * 4;
            float4 a = *reinterpret_cast<const float4*>(Wq + (c0 + cc) * NH + h4);
            float4 b = *reinterpret_cast<const float4*>(Wk + (c0 + cc) * NH + h4);
            float4 c = *reinterpret_cast<const float4*>(Wv + (c0 + cc) * NH + h4);
            *reinterpret_cast<float4*>(Ws + cc * 196 +       h4) = a;
            *reinterpret_cast<float4*>(Ws + cc * 196 +  64 + h4) = b;
            *reinterpret_cast<float4*>(Ws + cc * 196 + 128 + h4) = c;
        }
        __syncthreads();

#pragma unroll 4
        for (int cc = 0; cc < 64; ++cc) {
            float4 xa = *reinterpret_cast<const float4*>(Xs + cc * 128 + r0);
            float4 xb = *reinterpret_cast<const float4*>(Xs + cc * 128 + r0 + 4);
            float4 w0 = *reinterpret_cast<const float4*>(Ws + cc * 196 + hg * 12);
            float4 w1 = *reinterpret_cast<const float4*>(Ws + cc * 196 + hg * 12 + 4);
            float4 w2 = *reinterpret_cast<const float4*>(Ws + cc * 196 + hg * 12 + 8);
            float xs[8]  = {xa.x, xa.y, xa.z, xa.w, xb.x, xb.y, xb.z, xb.w};
            float ws[12] = {w0.x, w0.y, w0.z, w0.w, w1.x, w1.y, w1.z, w1.w,
                            w2.x, w2.y, w2.z, w2.w};
#pragma unroll
            for (int i = 0; i < 8; ++i)
#pragma unroll
                for (int j = 0; j < 12; ++j)
                    acc[i][j] = fmaf(xs[i], ws[j], acc[i][j]);
        }
        __syncthreads();
    }

#pragma unroll
    for (int i = 0; i < 8; ++i) {
        int row = row0 + r0 + i;
        int bb  = row >> 12;
        int tt  = row & (NT - 1);
#pragma unroll
        for (int j = 0; j < 12; ++j) {
            int col = hg * 12 + j;
            float v = acc[i][j];
            __nv_bfloat16 hi = __float2bfloat16(v);
            __nv_bfloat16 lo = __float2bfloat16(v - __bfloat162float(hi));
            if (col < 64) {
                g_qhi[row * NH + col] = hi;
                g_qlo[row * NH + col] = lo;
            } else if (col < 128) {
                int h = col - 64;
                g_khi[row * NH + h] = hi;
                g_klo[row * NH + h] = lo;
            } else {
                int h = col - 128;
                size_t idx = ((size_t)bb * NH + h) * NT + tt;
                g_vthi[idx] = hi;
                g_vtlo[idx] = lo;
            }
        }
    }
}

// ===========================================================================
// Kernel 2: mma.sync (HMMA bf16) causal attention, 3-term hi/lo split,
// unnormalized softmax (no running max; logits bounded, fp32 has headroom).
// Block: 256 threads (8 warps). Tile: 128 q-rows x 128 keys.
// Warp w owns q-rows [16w, 16w+16); S/P/O live entirely in registers.
// ===========================================================================
// smem layout (bytes). K: [128][72] bf16 (pad 8); Vt: [64][136] bf16 (pad 8).
#define SK_STRIDE 144            // 72 bf16
#define SV_STRIDE 272            // 136 bf16
#define SM_K_HI 0
#define SM_K_LO (SM_K_HI + 128 * SK_STRIDE)
#define SM_V_HI (SM_K_LO + 128 * SK_STRIDE)
#define SM_V_LO (SM_V_HI + 64 * SV_STRIDE)
#define SM_Q_HI (SM_V_LO + 64 * SV_STRIDE)
#define SM_Q_LO (SM_Q_HI + 128 * SK_STRIDE)
#define SM_ATT_TOTAL (SM_Q_LO + 128 * SK_STRIDE)   // 108544 B

__global__ __launch_bounds__(256, 1)
void attn_mma(float* __restrict__ out)
{
    extern __shared__ char smem[];
    const uint32_t sb = smem_u32(smem);

    const int t    = threadIdx.x;
    const int w    = t >> 5;
    const int lane = t & 31;
    const int qb   = 31 - blockIdx.x;      // longest blocks first
    const int b    = blockIdx.y;
    const int base = b * NT;
    const int q0   = qb * 128;

    // ---- stage Q tile (hi/lo) into smem ----
#pragma unroll
    for (int it = 0; it < 4; ++it) {
        int i   = t + it * 256;            // 0..1023 uint4
        int row = i >> 3;
        int c8  = (i & 7) * 8;
        uint32_t doff = row * SK_STRIDE + c8 * 2;
        size_t gi = (size_t)(base + q0 + row) * NH + c8;
        *reinterpret_cast<uint4*>(smem + SM_Q_HI + doff) =
            *reinterpret_cast<const uint4*>(g_qhi + gi);
        *reinterpret_cast<uint4*>(smem + SM_Q_LO + doff) =
            *reinterpret_cast<const uint4*>(g_qlo + gi);
    }
    __syncthreads();

    // ---- Q fragments (persist in registers for the whole kernel) ----
    // A-frag (m16k16) addresses: row = w*16 + (lane&15), col16 = (lane>>4)*16 + ks*32
    uint32_t qh[4][4], ql[4][4];
    {
        uint32_t qaddr = sb + (w * 16 + (lane & 15)) * SK_STRIDE + (lane >> 4) * 16;
#pragma unroll
        for (int ks = 0; ks < 4; ++ks) {
            ldsm_x4(qh[ks], qaddr + SM_Q_HI + ks * 32);
            ldsm_x4(ql[ks], qaddr + SM_Q_LO + ks * 32);
        }
    }

    // B-frag base addresses
    // K: key_row = 16*j2 + ((lane>>4)<<3) + (lane&7); h byte = ks*32 + ((lane>>3)&1)*16
    const uint32_t kbase = sb + ((((lane >> 4) << 3) + (lane & 7)) * SK_STRIDE) +
                           ((lane >> 3) & 1) * 16;
    // Vt: h_row = 16*jp + ((lane>>4)<<3) + (lane&7); key byte = kc*32 + ((lane>>3)&1)*16
    const uint32_t vbase = sb + ((((lane >> 4) << 3) + (lane & 7)) * SV_STRIDE) +
                           ((lane >> 3) & 1) * 16;

    float o[8][4];
#pragma unroll
    for (int j = 0; j < 8; ++j)
#pragma unroll
        for (int c = 0; c < 4; ++c) o[j][c] = 0.f;
    float l0 = 0.f, l1 = 0.f;

    const int ra = q0 + w * 16 + (lane >> 2);   // this thread's first abs q-row

    for (int kb = 0; kb <= qb; ++kb) {
        const int k0 = kb * 128;

        __syncthreads();   // prior iteration done reading K/V smem
        // ---- load K (hi/lo) [128][64] and Vt (hi/lo) [64][128] ----
#pragma unroll
        for (int it = 0; it < 4; ++it) {
            int i   = t + it * 256;
            int row = i >> 3;
            int c8  = (i & 7) * 8;
            uint32_t doff = row * SK_STRIDE + c8 * 2;
            size_t gi = (size_t)(base + k0 + row) * NH + c8;
            *reinterpret_cast<uint4*>(smem + SM_K_HI + doff) =
                *reinterpret_cast<const uint4*>(g_khi + gi);
            *reinterpret_cast<uint4*>(smem + SM_K_LO + doff) =
                *reinterpret_cast<const uint4*>(g_klo + gi);
        }
#pragma unroll
        for (int it = 0; it < 4; ++it) {
            int i  = t + it * 256;
            int h  = i >> 4;
            int k8 = (i & 15) * 8;
            uint32_t doff = h * SV_STRIDE + k8 * 2;
            size_t gi = ((size_t)b * NH + h) * NT + k0 + k8;
            *reinterpret_cast<uint4*>(smem + SM_V_HI + doff) =
                *reinterpret_cast<const uint4*>(g_vthi + gi);
            *reinterpret_cast<uint4*>(smem + SM_V_LO + doff) =
                *reinterpret_cast<const uint4*>(g_vtlo + gi);
        }
        __syncthreads();

        // ---- S = Q K^T  (16 n-tiles of 8 keys; 3 split terms) ----
        float s[16][4];
#pragma unroll
        for (int j = 0; j < 16; ++j)
#pragma unroll
            for (int c = 0; c < 4; ++c) s[j][c] = 0.f;

#pragma unroll
        for (int j2 = 0; j2 < 8; ++j2) {
            float* sA = s[2 * j2];
            float* sB = s[2 * j2 + 1];
#pragma unroll
            for (int ks = 0; ks < 4; ++ks) {
                uint32_t kh[4], kl[4];
                uint32_t a = kbase + j2 * (16 * SK_STRIDE) + ks * 32;
                ldsm_x4(kh, a + SM_K_HI);
                ldsm_x4(kl, a + SM_K_LO);
                mma_bf16(sA, qh[ks], kh[0], kh[1]);
                mma_bf16(sA, qh[ks], kl[0], kl[1]);
                mma_bf16(sA, ql[ks], kh[0], kh[1]);
                mma_bf16(sB, qh[ks], kh[2], kh[3]);
                mma_bf16(sB, qh[ks], kl[2], kl[3]);
                mma_bf16(sB, ql[ks], kh[2], kh[3]);
            }
        }

        // ---- exp (+ causal mask on diagonal block), accumulate row sums ----
        if (kb == qb) {
#pragma unroll
            for (int j = 0; j < 16; ++j) {
                int col = k0 + 8 * j + 2 * (lane & 3);
                float e0 = (col     <= ra)     ? __expf(s[j][0]) : 0.f;
                float e1 = (col + 1 <= ra)     ? __expf(s[j][1]) : 0.f;
                float e2 = (col     <= ra + 8) ? __expf(s[j][2]) : 0.f;
                float e3 = (col + 1 <= ra + 8) ? __expf(s[j][3]) : 0.f;
                s[j][0] = e0; s[j][1] = e1; s[j][2] = e2; s[j][3] = e3;
                l0 += e0 + e1;
                l1 += e2 + e3;
            }
        } else {
#pragma unroll
            for (int j = 0; j < 16; ++j) {
                float e0 = __expf(s[j][0]);
                float e1 = __expf(s[j][1]);
                float e2 = __expf(s[j][2]);
                float e3 = __expf(s[j][3]);
                s[j][0] = e0; s[j][1] = e1; s[j][2] = e2; s[j][3] = e3;
                l0 += e0 + e1;
                l1 += e2 + e3;
            }
        }

        // ---- O += P V : pack P (hi/lo) from accumulator frags, 3 split terms ----
#pragma unroll
        for (int kc = 0; kc < 8; ++kc) {
            uint32_t ah[4], al[4];
#pragma unroll
            for (int half = 0; half < 2; ++half) {
                const float* sp = s[2 * kc + half];
                float h0 = __bfloat162float(__float2bfloat16(sp[0]));
                float h1 = __bfloat162float(__float2bfloat16(sp[1]));
                float h2 = __bfloat162float(__float2bfloat16(sp[2]));
                float h3 = __bfloat162float(__float2bfloat16(sp[3]));
                ah[2 * half + 0] = pack_bf16x2(sp[0], sp[1]);
                ah[2 * half + 1] = pack_bf16x2(sp[2], sp[3]);
                al[2 * half + 0] = pack_bf16x2(sp[0] - h0, sp[1] - h1);
                al[2 * half + 1] = pack_bf16x2(sp[2] - h2, sp[3] - h3);
            }
#pragma unroll
            for (int jp = 0; jp < 4; ++jp) {
                uint32_t vh[4], vl[4];
                uint32_t a = vbase + jp * (16 * SV_STRIDE) + kc * 32;
                ldsm_x4(vh, a + SM_V_HI);
                ldsm_x4(vl, a + SM_V_LO);
                mma_bf16(o[2 * jp],     ah, vh[0], vh[1]);
                mma_bf16(o[2 * jp],     al, vh[0], vh[1]);
                mma_bf16(o[2 * jp],     ah, vl[0], vl[1]);
                mma_bf16(o[2 * jp + 1], ah, vh[2], vh[3]);
                mma_bf16(o[2 * jp + 1], al, vh[2], vh[3]);
                mma_bf16(o[2 * jp + 1], ah, vl[2], vl[3]);
            }
        }
    }

    // ---- finalize: reduce row sums across the 4-lane quad, normalize, store ----
    l0 += __shfl_xor_sync(0xffffffffu, l0, 1);
    l0 += __shfl_xor_sync(0xffffffffu, l0, 2);
    l1 += __shfl_xor_sync(0xffffffffu, l1, 1);
    l1 += __shfl_xor_sync(0xffffffffu, l1, 2);
    const float inv0 = 1.f / l0;
    const float inv1 = 1.f / l1;

    float* orow0 = out + (size_t)(base + ra) * NH;          // row ra
    float* orow1 = out + (size_t)(base + ra + 8) * NH;      // row ra+8
#pragma unroll
    for (int j = 0; j < 8; ++j) {
        int h = 8 * j + 2 * (lane & 3);
        *reinterpret_cast<float2*>(orow0 + h) =
            make_float2(o[j][0] * inv0, o[j][1] * inv0);
        *reinterpret_cast<float2*>(orow1 + h) =
            make_float2(o[j][2] * inv1, o[j][3] * inv1);
    }
}

// ===========================================================================
extern "C" void kernel_launch(void* const* d_in, const int* in_sizes, int n_in,
                              void* d_out, int out_size)
{
    (void)in_sizes; (void)n_in; (void)out_size;
    const float* x  = (const float*)d_in[0];
    const float* Wq = (const float*)d_in[1];
    const float* Wk = (const float*)d_in[2];
    const float* Wv = (const float*)d_in[3];
    float* out = (float*)d_out;

    const int smem1 = (64 * 128 + 64 * 196) * 4;  // 82944 B
    const int smem2 = SM_ATT_TOTAL;               // 108544 B
    cudaFuncSetAttribute(qkv_kernel, cudaFuncAttributeMaxDynamicSharedMemorySize, smem1);
    cudaFuncSetAttribute(attn_mma, cudaFuncAttributeMaxDynamicSharedMemorySize, smem2);

    qkv_kernel<<<128, 256, smem1>>>(x, Wq, Wk, Wv);
    attn_mma<<<dim3(32, NB), 256, smem2>>>(out);
}

// round 6
// speedup vs baseline: 3.1089x; 2.0345x over previous
#include <cuda_runtime.h>
#include <cuda_bf16.h>
#include <cstdint>

#define NB 4
#define NT 4096
#define NC 1024
#define NH 64
#define NROWS (NB * NT)

// bf16 hi/lo split q, k (row-major [row][h]); v transposed ([b][h][t]).
__device__ __nv_bfloat16 g_qhi[NROWS * NH];
__device__ __nv_bfloat16 g_qlo[NROWS * NH];
__device__ __nv_bfloat16 g_khi[NROWS * NH];
__device__ __nv_bfloat16 g_klo[NROWS * NH];
__device__ __nv_bfloat16 g_vthi[NB * NH * NT];
__device__ __nv_bfloat16 g_vtlo[NB * NH * NT];
// W transposed bf16 hi/lo: [192 cols][1024 c]  (q:0-63, k:64-127, v:128-191)
__device__ __nv_bfloat16 g_wthi[192 * NC];
__device__ __nv_bfloat16 g_wtlo[192 * NC];
// split-K partial accumulators
__device__ float g_oacc[NROWS * NH];
__device__ float g_lacc[NROWS];

// ===========================================================================
// Helpers (sm_80-era PTX: ldmatrix / mma.sync / cp.async — OK in compute_100)
// ===========================================================================
__device__ __forceinline__ uint32_t smem_u32(const void* p) {
    uint32_t a;
    asm("{ .reg .u64 t; cvta.to.shared.u64 t, %1; cvt.u32.u64 %0, t; }"
        : "=r"(a) : "l"(p));
    return a;
}
__device__ __forceinline__ void ldsm_x4(uint32_t* r, uint32_t addr) {
    asm volatile("ldmatrix.sync.aligned.m8n8.x4.shared.b16 {%0,%1,%2,%3}, [%4];"
                 : "=r"(r[0]), "=r"(r[1]), "=r"(r[2]), "=r"(r[3]) : "r"(addr));
}
__device__ __forceinline__ void mma_bf16(float* c, const uint32_t* a,
                                         uint32_t b0, uint32_t b1) {
    asm volatile(
        "mma.sync.aligned.m16n8k16.row.col.f32.bf16.bf16.f32 "
        "{%0,%1,%2,%3}, {%4,%5,%6,%7}, {%8,%9}, {%0,%1,%2,%3};"
        : "+f"(c[0]), "+f"(c[1]), "+f"(c[2]), "+f"(c[3])
        : "r"(a[0]), "r"(a[1]), "r"(a[2]), "r"(a[3]), "r"(b0), "r"(b1));
}
__device__ __forceinline__ uint32_t pack_bf16x2(float lo, float hi) {
    uint32_t r;
    asm("cvt.rn.bf16x2.f32 %0, %1, %2;" : "=r"(r) : "f"(hi), "f"(lo));
    return r;
}
#define CP16(dst, src) \
    asm volatile("cp.async.cg.shared.global [%0], [%1], 16;" :: "r"(dst), "l"(src))
#define CP_COMMIT() asm volatile("cp.async.commit_group;" ::: "memory")
#define CP_WAIT0()  asm volatile("cp.async.wait_group 0;" ::: "memory")

// ===========================================================================
// Kernel 0: init — zero split-K accumulators; build transposed bf16 hi/lo W.
// grid 256 x 256 threads = 65536
// ===========================================================================
__global__ void init_kernel(const float* __restrict__ Wq,
                            const float* __restrict__ Wk,
                            const float* __restrict__ Wv)
{
    const int tid = blockIdx.x * 256 + threadIdx.x;   // 0..65535
    float4 z = make_float4(0.f, 0.f, 0.f, 0.f);
#pragma unroll
    for (int i = tid; i < (NROWS * NH) / 4; i += 65536)
        reinterpret_cast<float4*>(g_oacc)[i] = z;
    if (tid < NROWS) g_lacc[tid] = 0.f;

    const int c = tid >> 6;      // 0..1023
    const int h = tid & 63;
    float wq = Wq[c * NH + h], wk = Wk[c * NH + h], wv = Wv[c * NH + h];
    __nv_bfloat16 h0 = __float2bfloat16(wq);
    __nv_bfloat16 h1 = __float2bfloat16(wk);
    __nv_bfloat16 h2 = __float2bfloat16(wv);
    g_wthi[(h)       * NC + c] = h0;
    g_wthi[(64 + h)  * NC + c] = h1;
    g_wthi[(128 + h) * NC + c] = h2;
    g_wtlo[(h)       * NC + c] = __float2bfloat16(wq - __bfloat162float(h0));
    g_wtlo[(64 + h)  * NC + c] = __float2bfloat16(wk - __bfloat162float(h1));
    g_wtlo[(128 + h) * NC + c] = __float2bfloat16(wv - __bfloat162float(h2));
}

// ===========================================================================
// Kernel 1: QKV projection via mma.sync bf16 3-term split.
// 128 blocks x 128 rows. 8 warps, warp w = rows [16w,16w+16), 24 n-tiles.
// smem: Xhi/Xlo [128][72]bf16 (stride 144 B), Wthi/Wtlo [192][72]bf16.
// ===========================================================================
#define QS_XHI 0
#define QS_XLO 18432
#define QS_WHI 36864
#define QS_WLO (36864 + 27648)
#define QS_TOTAL (QS_WLO + 27648)      // 92160 B

__global__ __launch_bounds__(256, 1)
void qkv_mma(const float* __restrict__ x)
{
    extern __shared__ char smem[];
    const uint32_t sb = smem_u32(smem);
    const int t    = threadIdx.x;
    const int w    = t >> 5;
    const int lane = t & 31;
    const int row0 = blockIdx.x * 128;

    float acc[24][4];
#pragma unroll
    for (int j = 0; j < 24; ++j)
#pragma unroll
        for (int c = 0; c < 4; ++c) acc[j][c] = 0.f;

    const uint32_t apat = (w * 16 + (lane & 15)) * 144 + (lane >> 4) * 16;
    const uint32_t bpat = ((((lane >> 4) << 3) + (lane & 7)) * 144) +
                          ((lane >> 3) & 1) * 16;

    for (int c0 = 0; c0 < NC; c0 += 64) {
        __syncthreads();
        // ---- x chunk: load fp32, convert to hi/lo bf16 ----
#pragma unroll
        for (int it = 0; it < 8; ++it) {
            int i   = t + it * 256;          // 0..2047 float4
            int row = i >> 4;
            int c4  = (i & 15) * 4;
            float4 v = *reinterpret_cast<const float4*>(
                x + (size_t)(row0 + row) * NC + c0 + c4);
            float hx = __bfloat162float(__float2bfloat16(v.x));
            float hy = __bfloat162float(__float2bfloat16(v.y));
            float hz = __bfloat162float(__float2bfloat16(v.z));
            float hw = __bfloat162float(__float2bfloat16(v.w));
            uint2 hi2 = make_uint2(pack_bf16x2(v.x, v.y), pack_bf16x2(v.z, v.w));
            uint2 lo2 = make_uint2(pack_bf16x2(v.x - hx, v.y - hy),
                                   pack_bf16x2(v.z - hz, v.w - hw));
            uint32_t doff = row * 144 + c4 * 2;
            *reinterpret_cast<uint2*>(smem + QS_XHI + doff) = hi2;
            *reinterpret_cast<uint2*>(smem + QS_XLO + doff) = lo2;
        }
        // ---- Wt chunk (bf16, coalesced) ----
#pragma unroll
        for (int it = 0; it < 6; ++it) {
            int i   = t + it * 256;          // 0..1535
            int col = i >> 3;
            int c8  = (i & 7) * 8;
            uint32_t doff = col * 144 + c8 * 2;
            *reinterpret_cast<uint4*>(smem + QS_WHI + doff) =
                *reinterpret_cast<const uint4*>(g_wthi + (size_t)col * NC + c0 + c8);
            *reinterpret_cast<uint4*>(smem + QS_WLO + doff) =
                *reinterpret_cast<const uint4*>(g_wtlo + (size_t)col * NC + c0 + c8);
        }
        __syncthreads();

        uint32_t ah[4][4], al[4][4];
#pragma unroll
        for (int ks = 0; ks < 4; ++ks) {
            ldsm_x4(ah[ks], sb + QS_XHI + apat + ks * 32);
            ldsm_x4(al[ks], sb + QS_XLO + apat + ks * 32);
        }
#pragma unroll
        for (int n2 = 0; n2 < 12; ++n2) {
            float* cA = acc[2 * n2];
            float* cB = acc[2 * n2 + 1];
#pragma unroll
            for (int ks = 0; ks < 4; ++ks) {
                uint32_t bh[4], bl[4];
                uint32_t a = sb + bpat + n2 * (16 * 144) + ks * 32;
                ldsm_x4(bh, a + QS_WHI);
                ldsm_x4(bl, a + QS_WLO);
                mma_bf16(cA, ah[ks], bh[0], bh[1]);
                mma_bf16(cA, ah[ks], bl[0], bl[1]);
                mma_bf16(cA, al[ks], bh[0], bh[1]);
                mma_bf16(cB, ah[ks], bh[2], bh[3]);
                mma_bf16(cB, ah[ks], bl[2], bl[3]);
                mma_bf16(cB, al[ks], bh[2], bh[3]);
            }
        }
    }

    // ---- epilogue: split each result to bf16 hi/lo and scatter ----
    const int ra = row0 + w * 16 + (lane >> 2);
#pragma unroll
    for (int j = 0; j < 24; ++j) {
        int col = 8 * j + 2 * (lane & 3);
#pragma unroll
        for (int half = 0; half < 2; ++half) {
            int row = ra + 8 * half;
            float v0 = acc[j][2 * half], v1 = acc[j][2 * half + 1];
            float h0 = __bfloat162float(__float2bfloat16(v0));
            float h1 = __bfloat162float(__float2bfloat16(v1));
            uint32_t hi = pack_bf16x2(v0, v1);
            uint32_t lo = pack_bf16x2(v0 - h0, v1 - h1);
            if (col < 64) {
                *reinterpret_cast<uint32_t*>(g_qhi + (size_t)row * NH + col) = hi;
                *reinterpret_cast<uint32_t*>(g_qlo + (size_t)row * NH + col) = lo;
            } else if (col < 128) {
                *reinterpret_cast<uint32_t*>(g_khi + (size_t)row * NH + col - 64) = hi;
                *reinterpret_cast<uint32_t*>(g_klo + (size_t)row * NH + col - 64) = lo;
            } else {
                int h  = col - 128;
                int bb = row >> 12, tt = row & (NT - 1);
                size_t i0 = ((size_t)bb * NH + h) * NT + tt;
                g_vthi[i0]      = __float2bfloat16(v0);
                g_vtlo[i0]      = __float2bfloat16(v0 - h0);
                g_vthi[i0 + NT] = __float2bfloat16(v1);
                g_vtlo[i0 + NT] = __float2bfloat16(v1 - h1);
            }
        }
    }
}

// ===========================================================================
// Kernel 2: balanced split-K causal attention (mma.sync, 3-term split,
// unnormalized softmax). 2112 (b,qtile,ktile) iterations, 132 blocks x 16.
// Partial O,l accumulated to g_oacc/g_lacc via atomicAdd at tile boundaries.
// Double-buffered cp.async K/V stages.
// ===========================================================================
#define STG_KHI 0
#define STG_KLO 18432
#define STG_VHI 36864
#define STG_VLO 54272
#define STG_SZ  71680
#define SM_Q_HI (2 * STG_SZ)           // 143360
#define SM_Q_LO (SM_Q_HI + 18432)
#define SM_ATT_TOTAL (SM_Q_LO + 18432) // 180224 B

__global__ __launch_bounds__(256, 1)
void attn_mma()
{
    extern __shared__ char smem[];
    const uint32_t sb = smem_u32(smem);
    const int t    = threadIdx.x;
    const int w    = t >> 5;
    const int lane = t & 31;

    // ---- decode starting (b, qb, kb) from linear iteration index ----
    int g0 = blockIdx.x * 16;
    int b  = g0 / 528;
    int r  = g0 - 528 * b;
    int qb = (int)((sqrtf(8.f * (float)r + 1.f) - 1.f) * 0.5f);
    while ((qb + 1) * (qb + 2) / 2 <= r) ++qb;
    while (qb * (qb + 1) / 2 > r) --qb;
    int kb = r - qb * (qb + 1) / 2;

    const uint32_t kpat = ((((lane >> 4) << 3) + (lane & 7)) * 144) +
                          ((lane >> 3) & 1) * 16;
    const uint32_t vpat = ((((lane >> 4) << 3) + (lane & 7)) * 272) +
                          ((lane >> 3) & 1) * 16;
    const uint32_t qpat = (w * 16 + (lane & 15)) * 144 + (lane >> 4) * 16;

    // ---- K/V stage prefetch ----
    auto issue_kv = [&](int stage, int bb, int kbb) {
        uint32_t st = sb + stage * STG_SZ;
        int k0 = kbb * 128;
        const __nv_bfloat16* kh = g_khi + ((size_t)bb * NT + k0) * NH;
        const __nv_bfloat16* kl = g_klo + ((size_t)bb * NT + k0) * NH;
#pragma unroll
        for (int it = 0; it < 4; ++it) {
            int i   = t + it * 256;
            int row = i >> 3;
            int c8  = (i & 7) * 8;
            uint32_t doff = row * 144 + c8 * 2;
            CP16(st + STG_KHI + doff, kh + row * NH + c8);
            CP16(st + STG_KLO + doff, kl + row * NH + c8);
        }
        const __nv_bfloat16* vh = g_vthi + (size_t)bb * NH * NT + k0;
        const __nv_bfloat16* vl = g_vtlo + (size_t)bb * NH * NT + k0;
#pragma unroll
        for (int it = 0; it < 4; ++it) {
            int i  = t + it * 256;
            int h  = i >> 4;
            int k8 = (i & 15) * 8;
            uint32_t doff = h * 272 + k8 * 2;
            CP16(st + STG_VHI + doff, vh + (size_t)h * NT + k8);
            CP16(st + STG_VLO + doff, vl + (size_t)h * NT + k8);
        }
    };
    auto load_q = [&](int bb, int qbb) {
        const __nv_bfloat16* qh = g_qhi + ((size_t)bb * NT + qbb * 128) * NH;
        const __nv_bfloat16* ql = g_qlo + ((size_t)bb * NT + qbb * 128) * NH;
#pragma unroll
        for (int it = 0; it < 4; ++it) {
            int i   = t + it * 256;
            int row = i >> 3;
            int c8  = (i & 7) * 8;
            uint32_t doff = row * 144 + c8 * 2;
            *reinterpret_cast<uint4*>(smem + SM_Q_HI + doff) =
                *reinterpret_cast<const uint4*>(qh + row * NH + c8);
            *reinterpret_cast<uint4*>(smem + SM_Q_LO + doff) =
                *reinterpret_cast<const uint4*>(ql + row * NH + c8);
        }
    };

    uint32_t qh[4][4], ql[4][4];
    auto build_q = [&]() {
#pragma unroll
        for (int ks = 0; ks < 4; ++ks) {
            ldsm_x4(qh[ks], sb + SM_Q_HI + qpat + ks * 32);
            ldsm_x4(ql[ks], sb + SM_Q_LO + qpat + ks * 32);
        }
    };

    float o[8][4], l0, l1;
    auto zero_acc = [&]() {
#pragma unroll
        for (int j = 0; j < 8; ++j)
#pragma unroll
            for (int c = 0; c < 4; ++c) o[j][c] = 0.f;
        l0 = l1 = 0.f;
    };
    auto flush = [&](int bb, int qbb) {
        // Row sums are spread across the 4-lane quad (each lane covers 2 of 8
        // columns per n-tile). Reduce across the quad BEFORE the single-lane
        // atomicAdd — omitting this was the R5 correctness bug.
        float r0 = l0, r1 = l1;
        r0 += __shfl_xor_sync(0xffffffffu, r0, 1);
        r0 += __shfl_xor_sync(0xffffffffu, r0, 2);
        r1 += __shfl_xor_sync(0xffffffffu, r1, 1);
        r1 += __shfl_xor_sync(0xffffffffu, r1, 2);
        int rra = bb * NT + qbb * 128 + w * 16 + (lane >> 2);
        if ((lane & 3) == 0) {
            atomicAdd(&g_lacc[rra], r0);
            atomicAdd(&g_lacc[rra + 8], r1);
        }
        float* o0 = g_oacc + (size_t)rra * NH;
        float* o1 = g_oacc + (size_t)(rra + 8) * NH;
#pragma unroll
        for (int j = 0; j < 8; ++j) {
            int h = 8 * j + 2 * (lane & 3);
            atomicAdd(o0 + h,     o[j][0]);
            atomicAdd(o0 + h + 1, o[j][1]);
            atomicAdd(o1 + h,     o[j][2]);
            atomicAdd(o1 + h + 1, o[j][3]);
        }
    };

    // ---- prologue ----
    issue_kv(0, b, kb);
    CP_COMMIT();
    load_q(b, qb);
    __syncthreads();
    build_q();
    zero_acc();

    for (int it = 0; it < 16; ++it) {
        CP_WAIT0();
        __syncthreads();

        int nb = b, nqb = qb, nkb = kb + 1;
        bool changed = false;
        if (nkb > nqb) {
            nkb = 0; ++nqb; changed = true;
            if (nqb == 32) { nqb = 0; ++nb; }
        }
        if (it < 15) { issue_kv((it + 1) & 1, nb, nkb); CP_COMMIT(); }

        const uint32_t st = sb + (it & 1) * STG_SZ;
        const int k0 = kb * 128;
        const int ra = qb * 128 + w * 16 + (lane >> 2);

        // ---- S = Q K^T ----
        float s[16][4];
#pragma unroll
        for (int j = 0; j < 16; ++j)
#pragma unroll
            for (int c = 0; c < 4; ++c) s[j][c] = 0.f;
#pragma unroll
        for (int j2 = 0; j2 < 8; ++j2) {
            float* sA = s[2 * j2];
            float* sB = s[2 * j2 + 1];
#pragma unroll
            for (int ks = 0; ks < 4; ++ks) {
                uint32_t kh[4], kl[4];
                uint32_t a = st + kpat + j2 * (16 * 144) + ks * 32;
                ldsm_x4(kh, a + STG_KHI);
                ldsm_x4(kl, a + STG_KLO);
                mma_bf16(sA, qh[ks], kh[0], kh[1]);
                mma_bf16(sA, qh[ks], kl[0], kl[1]);
                mma_bf16(sA, ql[ks], kh[0], kh[1]);
                mma_bf16(sB, qh[ks], kh[2], kh[3]);
                mma_bf16(sB, qh[ks], kl[2], kl[3]);
                mma_bf16(sB, ql[ks], kh[2], kh[3]);
            }
        }

        // ---- exp (+ causal mask on diagonal tile) ----
        if (kb == qb) {
#pragma unroll
            for (int j = 0; j < 16; ++j) {
                int col = k0 + 8 * j + 2 * (lane & 3);
                float e0 = (col     <= ra)     ? __expf(s[j][0]) : 0.f;
                float e1 = (col + 1 <= ra)     ? __expf(s[j][1]) : 0.f;
                float e2 = (col     <= ra + 8) ? __expf(s[j][2]) : 0.f;
                float e3 = (col + 1 <= ra + 8) ? __expf(s[j][3]) : 0.f;
                s[j][0] = e0; s[j][1] = e1; s[j][2] = e2; s[j][3] = e3;
                l0 += e0 + e1; l1 += e2 + e3;
            }
        } else {
#pragma unroll
            for (int j = 0; j < 16; ++j) {
                float e0 = __expf(s[j][0]);
                float e1 = __expf(s[j][1]);
                float e2 = __expf(s[j][2]);
                float e3 = __expf(s[j][3]);
                s[j][0] = e0; s[j][1] = e1; s[j][2] = e2; s[j][3] = e3;
                l0 += e0 + e1; l1 += e2 + e3;
            }
        }

        // ---- O += P V ----
#pragma unroll
        for (int kc = 0; kc < 8; ++kc) {
            uint32_t ah[4], al[4];
#pragma unroll
            for (int half = 0; half < 2; ++half) {
                const float* sp = s[2 * kc + half];
                float h0 = __bfloat162float(__float2bfloat16(sp[0]));
                float h1 = __bfloat162float(__float2bfloat16(sp[1]));
                float h2 = __bfloat162float(__float2bfloat16(sp[2]));
                float h3 = __bfloat162float(__float2bfloat16(sp[3]));
                ah[2 * half + 0] = pack_bf16x2(sp[0], sp[1]);
                ah[2 * half + 1] = pack_bf16x2(sp[2], sp[3]);
                al[2 * half + 0] = pack_bf16x2(sp[0] - h0, sp[1] - h1);
                al[2 * half + 1] = pack_bf16x2(sp[2] - h2, sp[3] - h3);
            }
#pragma unroll
            for (int jp = 0; jp < 4; ++jp) {
                uint32_t vh[4], vl[4];
                uint32_t a = st + STG_VHI + vpat + jp * (16 * 272) + kc * 32;
                ldsm_x4(vh, a);
                ldsm_x4(vl, a + (STG_VLO - STG_VHI));
                mma_bf16(o[2 * jp],     ah, vh[0], vh[1]);
                mma_bf16(o[2 * jp],     al, vh[0], vh[1]);
                mma_bf16(o[2 * jp],     ah, vl[0], vl[1]);
                mma_bf16(o[2 * jp + 1], ah, vh[2], vh[3]);
                mma_bf16(o[2 * jp + 1], al, vh[2], vh[3]);
                mma_bf16(o[2 * jp + 1], ah, vl[2], vl[3]);
            }
        }

        if (it < 15) {
            if (changed) {
                flush(b, qb);
                load_q(nb, nqb);
                __syncthreads();
                build_q();
                zero_acc();
            }
            b = nb; qb = nqb; kb = nkb;
        }
    }
    flush(b, qb);
}

// ===========================================================================
// Kernel 3: normalize — out = O / l
// ===========================================================================
__global__ void norm_kernel(float* __restrict__ out)
{
    const int tid = blockIdx.x * 256 + threadIdx.x;     // 65536 threads
#pragma unroll
    for (int i = tid; i < (NROWS * NH) / 4; i += 65536) {
        float4 v = reinterpret_cast<const float4*>(g_oacc)[i];
        float linv = 1.f / g_lacc[(i * 4) >> 6];
        v.x *= linv; v.y *= linv; v.z *= linv; v.w *= linv;
        reinterpret_cast<float4*>(out)[i] = v;
    }
}

// ===========================================================================
extern "C" void kernel_launch(void* const* d_in, const int* in_sizes, int n_in,
                              void* d_out, int out_size)
{
    (void)in_sizes; (void)n_in; (void)out_size;
    const float* x  = (const float*)d_in[0];
    const float* Wq = (const float*)d_in[1];
    const float* Wk = (const float*)d_in[2];
    const float* Wv = (const float*)d_in[3];
    float* out = (float*)d_out;

    cudaFuncSetAttribute(qkv_mma, cudaFuncAttributeMaxDynamicSharedMemorySize, QS_TOTAL);
    cudaFuncSetAttribute(attn_mma, cudaFuncAttributeMaxDynamicSharedMemorySize, SM_ATT_TOTAL);

    init_kernel<<<256, 256>>>(Wq, Wk, Wv);
    qkv_mma<<<128, 256, QS_TOTAL>>>(x);
    attn_mma<<<132, 256, SM_ATT_TOTAL>>>();
    norm_kernel<<<256, 256>>>(out);
}

// round 8
// speedup vs baseline: 3.1747x; 1.0212x over previous
#include <cuda_runtime.h>
#include <cuda_bf16.h>
#include <cstdint>

#define NB 4
#define NT 4096
#define NC 1024
#define NH 64
#define NROWS (NB * NT)

// bf16 hi/lo split q, k (row-major [row][h]); v transposed ([b][h][t]).
__device__ __nv_bfloat16 g_qhi[NROWS * NH];
__device__ __nv_bfloat16 g_qlo[NROWS * NH];
__device__ __nv_bfloat16 g_khi[NROWS * NH];
__device__ __nv_bfloat16 g_klo[NROWS * NH];
__device__ __nv_bfloat16 g_vthi[NB * NH * NT];
__device__ __nv_bfloat16 g_vtlo[NB * NH * NT];
// W transposed bf16 hi/lo: [192 cols][1024 c]  (q:0-63, k:64-127, v:128-191)
__device__ __nv_bfloat16 g_wthi[192 * NC];
__device__ __nv_bfloat16 g_wtlo[192 * NC];
// split-K partial accumulators
__device__ float g_oacc[NROWS * NH];
__device__ float g_lacc[NROWS];

// ===========================================================================
// Helpers (sm_80-era PTX: ldmatrix / mma.sync / cp.async — OK in compute_100)
// ===========================================================================
__device__ __forceinline__ uint32_t smem_u32(const void* p) {
    uint32_t a;
    asm("{ .reg .u64 t; cvta.to.shared.u64 t, %1; cvt.u32.u64 %0, t; }"
        : "=r"(a) : "l"(p));
    return a;
}
__device__ __forceinline__ void ldsm_x4(uint32_t* r, uint32_t addr) {
    asm volatile("ldmatrix.sync.aligned.m8n8.x4.shared.b16 {%0,%1,%2,%3}, [%4];"
                 : "=r"(r[0]), "=r"(r[1]), "=r"(r[2]), "=r"(r[3]) : "r"(addr));
}
__device__ __forceinline__ void mma_bf16(float* c, const uint32_t* a,
                                         uint32_t b0, uint32_t b1) {
    asm volatile(
        "mma.sync.aligned.m16n8k16.row.col.f32.bf16.bf16.f32 "
        "{%0,%1,%2,%3}, {%4,%5,%6,%7}, {%8,%9}, {%0,%1,%2,%3};"
        : "+f"(c[0]), "+f"(c[1]), "+f"(c[2]), "+f"(c[3])
        : "r"(a[0]), "r"(a[1]), "r"(a[2]), "r"(a[3]), "r"(b0), "r"(b1));
}
__device__ __forceinline__ uint32_t pack_bf16x2(float lo, float hi) {
    uint32_t r;
    asm("cvt.rn.bf16x2.f32 %0, %1, %2;" : "=r"(r) : "f"(hi), "f"(lo));
    return r;
}
#define CP16(dst, src) \
    asm volatile("cp.async.cg.shared.global [%0], [%1], 16;" :: "r"(dst), "l"(src))
#define CP_COMMIT() asm volatile("cp.async.commit_group;" ::: "memory")
#define CP_WAIT0()  asm volatile("cp.async.wait_group 0;" ::: "memory")
#define CP_WAIT1()  asm volatile("cp.async.wait_group 1;" ::: "memory")

// ===========================================================================
// Kernel 0: init — zero split-K accumulators; build transposed bf16 hi/lo W.
// grid 512 x 256 threads = 131072
// ===========================================================================
__global__ void init_kernel(const float* __restrict__ Wq,
                            const float* __restrict__ Wk,
                            const float* __restrict__ Wv)
{
    const int tid = blockIdx.x * 256 + threadIdx.x;   // 0..131071
    float4 z = make_float4(0.f, 0.f, 0.f, 0.f);
#pragma unroll
    for (int i = tid; i < (NROWS * NH) / 4; i += 131072)
        reinterpret_cast<float4*>(g_oacc)[i] = z;
    if (tid < NROWS) g_lacc[tid] = 0.f;

    if (tid < 65536) {
        const int c = tid >> 6;      // 0..1023
        const int h = tid & 63;
        float wq = Wq[c * NH + h], wk = Wk[c * NH + h], wv = Wv[c * NH + h];
        __nv_bfloat16 h0 = __float2bfloat16(wq);
        __nv_bfloat16 h1 = __float2bfloat16(wk);
        __nv_bfloat16 h2 = __float2bfloat16(wv);
        g_wthi[(h)       * NC + c] = h0;
        g_wthi[(64 + h)  * NC + c] = h1;
        g_wthi[(128 + h) * NC + c] = h2;
        g_wtlo[(h)       * NC + c] = __float2bfloat16(wq - __bfloat162float(h0));
        g_wtlo[(64 + h)  * NC + c] = __float2bfloat16(wk - __bfloat162float(h1));
        g_wtlo[(128 + h) * NC + c] = __float2bfloat16(wv - __bfloat162float(h2));
    }
}

// ===========================================================================
// Kernel 1: QKV projection via mma.sync bf16 3-term split.
// 128 blocks x 128 rows. 8 warps, warp w = rows [16w,16w+16), 24 n-tiles.
// x chunk: register double-buffer (prefetch next during MMA phase).
// W chunks: cp.async, 2 smem stages. The refill of a W stage is issued ONLY
// after the barrier that proves all warps finished the MMA reading it
// (issuing before that barrier was the R7 race).
// smem: Xhi/Xlo [128][72]bf16 + W stages 2 x ([192][72] hi + lo).
// ===========================================================================
#define QS_XHI 0
#define QS_XLO 18432
#define QS_W   36864
#define QS_WSTG 55296                  // hi (27648) + lo (27648)
#define QS_TOTAL (QS_W + 2 * QS_WSTG)  // 147456 B

__global__ __launch_bounds__(256, 1)
void qkv_mma(const float* __restrict__ x)
{
    extern __shared__ char smem[];
    const uint32_t sb = smem_u32(smem);
    const int t    = threadIdx.x;
    const int w    = t >> 5;
    const int lane = t & 31;
    const int row0 = blockIdx.x * 128;

    float acc[24][4];
#pragma unroll
    for (int j = 0; j < 24; ++j)
#pragma unroll
        for (int c = 0; c < 4; ++c) acc[j][c] = 0.f;

    const uint32_t apat = (w * 16 + (lane & 15)) * 144 + (lane >> 4) * 16;
    const uint32_t bpat = ((((lane >> 4) << 3) + (lane & 7)) * 144) +
                          ((lane >> 3) & 1) * 16;

    float4 xreg[8];
    auto load_x = [&](int c0) {
#pragma unroll
        for (int it = 0; it < 8; ++it) {
            int i   = t + it * 256;          // 0..2047 float4
            int row = i >> 4;
            int c4  = (i & 15) * 4;
            xreg[it] = *reinterpret_cast<const float4*>(
                x + (size_t)(row0 + row) * NC + c0 + c4);
        }
    };
    auto store_x = [&]() {
#pragma unroll
        for (int it = 0; it < 8; ++it) {
            int i   = t + it * 256;
            int row = i >> 4;
            int c4  = (i & 15) * 4;
            float4 v = xreg[it];
            float hx = __bfloat162float(__float2bfloat16(v.x));
            float hy = __bfloat162float(__float2bfloat16(v.y));
            float hz = __bfloat162float(__float2bfloat16(v.z));
            float hw = __bfloat162float(__float2bfloat16(v.w));
            uint2 hi2 = make_uint2(pack_bf16x2(v.x, v.y), pack_bf16x2(v.z, v.w));
            uint2 lo2 = make_uint2(pack_bf16x2(v.x - hx, v.y - hy),
                                   pack_bf16x2(v.z - hz, v.w - hw));
            uint32_t doff = row * 144 + c4 * 2;
            *reinterpret_cast<uint2*>(smem + QS_XHI + doff) = hi2;
            *reinterpret_cast<uint2*>(smem + QS_XLO + doff) = lo2;
        }
    };
    auto issue_w = [&](int stage, int c0) {
        uint32_t st = sb + QS_W + stage * QS_WSTG;
#pragma unroll
        for (int it = 0; it < 6; ++it) {
            int i   = t + it * 256;          // 0..1535
            int col = i >> 3;
            int c8  = (i & 7) * 8;
            uint32_t doff = col * 144 + c8 * 2;
            CP16(st + doff,         g_wthi + (size_t)col * NC + c0 + c8);
            CP16(st + 27648 + doff, g_wtlo + (size_t)col * NC + c0 + c8);
        }
    };

    // prologue
    issue_w(0, 0);
    CP_COMMIT();
    load_x(0);

    for (int c = 0; c < 16; ++c) {
        const int c0 = c * 64;
        __syncthreads();               // ALL warps done with prior MMA phase
                                       // (X smem AND the W stage we now refill)
        if (c < 15) { issue_w((c + 1) & 1, c0 + 64); CP_COMMIT(); }
        store_x();                     // convert + store chunk c
        if (c < 15) load_x(c0 + 64);   // prefetch next chunk (lands during MMA)
        if (c < 15) { CP_WAIT1(); } else { CP_WAIT0(); }
        __syncthreads();

        const uint32_t wst = sb + QS_W + (c & 1) * QS_WSTG;
        uint32_t ah[4][4], al[4][4];
#pragma unroll
        for (int ks = 0; ks < 4; ++ks) {
            ldsm_x4(ah[ks], sb + QS_XHI + apat + ks * 32);
            ldsm_x4(al[ks], sb + QS_XLO + apat + ks * 32);
        }
#pragma unroll
        for (int n2 = 0; n2 < 12; ++n2) {
            float* cA = acc[2 * n2];
            float* cB = acc[2 * n2 + 1];
#pragma unroll
            for (int ks = 0; ks < 4; ++ks) {
                uint32_t bh[4], bl[4];
                uint32_t a = wst + bpat + n2 * (16 * 144) + ks * 32;
                ldsm_x4(bh, a);
                ldsm_x4(bl, a + 27648);
                mma_bf16(cA, ah[ks], bh[0], bh[1]);
                mma_bf16(cA, ah[ks], bl[0], bl[1]);
                mma_bf16(cA, al[ks], bh[0], bh[1]);
                mma_bf16(cB, ah[ks], bh[2], bh[3]);
                mma_bf16(cB, ah[ks], bl[2], bl[3]);
                mma_bf16(cB, al[ks], bh[2], bh[3]);
            }
        }
    }

    // ---- epilogue: split each result to bf16 hi/lo and scatter ----
    const int ra = row0 + w * 16 + (lane >> 2);
#pragma unroll
    for (int j = 0; j < 24; ++j) {
        int col = 8 * j + 2 * (lane & 3);
#pragma unroll
        for (int half = 0; half < 2; ++half) {
            int row = ra + 8 * half;
            float v0 = acc[j][2 * half], v1 = acc[j][2 * half + 1];
            float h0 = __bfloat162float(__float2bfloat16(v0));
            float h1 = __bfloat162float(__float2bfloat16(v1));
            uint32_t hi = pack_bf16x2(v0, v1);
            uint32_t lo = pack_bf16x2(v0 - h0, v1 - h1);
            if (col < 64) {
                *reinterpret_cast<uint32_t*>(g_qhi + (size_t)row * NH + col) = hi;
                *reinterpret_cast<uint32_t*>(g_qlo + (size_t)row * NH + col) = lo;
            } else if (col < 128) {
                *reinterpret_cast<uint32_t*>(g_khi + (size_t)row * NH + col - 64) = hi;
                *reinterpret_cast<uint32_t*>(g_klo + (size_t)row * NH + col - 64) = lo;
            } else {
                int h  = col - 128;
                int bb = row >> 12, tt = row & (NT - 1);
                size_t i0 = ((size_t)bb * NH + h) * NT + tt;
                g_vthi[i0]      = __float2bfloat16(v0);
                g_vtlo[i0]      = __float2bfloat16(v0 - h0);
                g_vthi[i0 + NT] = __float2bfloat16(v1);
                g_vtlo[i0 + NT] = __float2bfloat16(v1 - h1);
            }
        }
    }
}

// ===========================================================================
// Kernel 2: balanced split-K causal attention (mma.sync, 3-term split,
// unnormalized softmax). 2112 (b,qtile,ktile) iterations, 132 blocks x 16.
// Partial O,l accumulated to g_oacc/g_lacc via atomicAdd at tile boundaries.
// Double-buffered cp.async K/V stages.
// ===========================================================================
#define STG_KHI 0
#define STG_KLO 18432
#define STG_VHI 36864
#define STG_VLO 54272
#define STG_SZ  71680
#define SM_Q_HI (2 * STG_SZ)           // 143360
#define SM_Q_LO (SM_Q_HI + 18432)
#define SM_ATT_TOTAL (SM_Q_LO + 18432) // 180224 B

__global__ __launch_bounds__(256, 1)
void attn_mma()
{
    extern __shared__ char smem[];
    const uint32_t sb = smem_u32(smem);
    const int t    = threadIdx.x;
    const int w    = t >> 5;
    const int lane = t & 31;

    // ---- decode starting (b, qb, kb) from linear iteration index ----
    int g0 = blockIdx.x * 16;
    int b  = g0 / 528;
    int r  = g0 - 528 * b;
    int qb = (int)((sqrtf(8.f * (float)r + 1.f) - 1.f) * 0.5f);
    while ((qb + 1) * (qb + 2) / 2 <= r) ++qb;
    while (qb * (qb + 1) / 2 > r) --qb;
    int kb = r - qb * (qb + 1) / 2;

    const uint32_t kpat = ((((lane >> 4) << 3) + (lane & 7)) * 144) +
                          ((lane >> 3) & 1) * 16;
    const uint32_t vpat = ((((lane >> 4) << 3) + (lane & 7)) * 272) +
                          ((lane >> 3) & 1) * 16;
    const uint32_t qpat = (w * 16 + (lane & 15)) * 144 + (lane >> 4) * 16;

    // ---- K/V stage prefetch ----
    auto issue_kv = [&](int stage, int bb, int kbb) {
        uint32_t st = sb + stage * STG_SZ;
        int k0 = kbb * 128;
        const __nv_bfloat16* kh = g_khi + ((size_t)bb * NT + k0) * NH;
        const __nv_bfloat16* kl = g_klo + ((size_t)bb * NT + k0) * NH;
#pragma unroll
        for (int it = 0; it < 4; ++it) {
            int i   = t + it * 256;
            int row = i >> 3;
            int c8  = (i & 7) * 8;
            uint32_t doff = row * 144 + c8 * 2;
            CP16(st + STG_KHI + doff, kh + row * NH + c8);
            CP16(st + STG_KLO + doff, kl + row * NH + c8);
        }
        const __nv_bfloat16* vh = g_vthi + (size_t)bb * NH * NT + k0;
        const __nv_bfloat16* vl = g_vtlo + (size_t)bb * NH * NT + k0;
#pragma unroll
        for (int it = 0; it < 4; ++it) {
            int i  = t + it * 256;
            int h  = i >> 4;
            int k8 = (i & 15) * 8;
            uint32_t doff = h * 272 + k8 * 2;
            CP16(st + STG_VHI + doff, vh + (size_t)h * NT + k8);
            CP16(st + STG_VLO + doff, vl + (size_t)h * NT + k8);
        }
    };
    auto load_q = [&](int bb, int qbb) {
        const __nv_bfloat16* qh = g_qhi + ((size_t)bb * NT + qbb * 128) * NH;
        const __nv_bfloat16* ql = g_qlo + ((size_t)bb * NT + qbb * 128) * NH;
#pragma unroll
        for (int it = 0; it < 4; ++it) {
            int i   = t + it * 256;
            int row = i >> 3;
            int c8  = (i & 7) * 8;
            uint32_t doff = row * 144 + c8 * 2;
            *reinterpret_cast<uint4*>(smem + SM_Q_HI + doff) =
                *reinterpret_cast<const uint4*>(qh + row * NH + c8);
            *reinterpret_cast<uint4*>(smem + SM_Q_LO + doff) =
                *reinterpret_cast<const uint4*>(ql + row * NH + c8);
        }
    };

    uint32_t qh[4][4], ql[4][4];
    auto build_q = [&]() {
#pragma unroll
        for (int ks = 0; ks < 4; ++ks) {
            ldsm_x4(qh[ks], sb + SM_Q_HI + qpat + ks * 32);
            ldsm_x4(ql[ks], sb + SM_Q_LO + qpat + ks * 32);
        }
    };

    float o[8][4], l0, l1;
    auto zero_acc = [&]() {
#pragma unroll
        for (int j = 0; j < 8; ++j)
#pragma unroll
            for (int c = 0; c < 4; ++c) o[j][c] = 0.f;
        l0 = l1 = 0.f;
    };
    auto flush = [&](int bb, int qbb) {
        // Reduce row sums across the 4-lane quad BEFORE the single-lane
        // atomicAdd (each lane covers only 2 of 8 columns per n-tile).
        float r0 = l0, r1 = l1;
        r0 += __shfl_xor_sync(0xffffffffu, r0, 1);
        r0 += __shfl_xor_sync(0xffffffffu, r0, 2);
        r1 += __shfl_xor_sync(0xffffffffu, r1, 1);
        r1 += __shfl_xor_sync(0xffffffffu, r1, 2);
        int rra = bb * NT + qbb * 128 + w * 16 + (lane >> 2);
        if ((lane & 3) == 0) {
            atomicAdd(&g_lacc[rra], r0);
            atomicAdd(&g_lacc[rra + 8], r1);
        }
        float* o0 = g_oacc + (size_t)rra * NH;
        float* o1 = g_oacc + (size_t)(rra + 8) * NH;
#pragma unroll
        for (int j = 0; j < 8; ++j) {
            int h = 8 * j + 2 * (lane & 3);
            atomicAdd(o0 + h,     o[j][0]);
            atomicAdd(o0 + h + 1, o[j][1]);
            atomicAdd(o1 + h,     o[j][2]);
            atomicAdd(o1 + h + 1, o[j][3]);
        }
    };

    // ---- prologue ----
    issue_kv(0, b, kb);
    CP_COMMIT();
    load_q(b, qb);
    __syncthreads();
    build_q();
    zero_acc();

    for (int it = 0; it < 16; ++it) {
        CP_WAIT0();
        __syncthreads();

        int nb = b, nqb = qb, nkb = kb + 1;
        bool changed = false;
        if (nkb > nqb) {
            nkb = 0; ++nqb; changed = true;
            if (nqb == 32) { nqb = 0; ++nb; }
        }
        if (it < 15) { issue_kv((it + 1) & 1, nb, nkb); CP_COMMIT(); }

        const uint32_t st = sb + (it & 1) * STG_SZ;
        const int k0 = kb * 128;
        const int ra = qb * 128 + w * 16 + (lane >> 2);

        // ---- S = Q K^T ----
        float s[16][4];
#pragma unroll
        for (int j = 0; j < 16; ++j)
#pragma unroll
            for (int c = 0; c < 4; ++c) s[j][c] = 0.f;
#pragma unroll
        for (int j2 = 0; j2 < 8; ++j2) {
            float* sA = s[2 * j2];
            float* sB = s[2 * j2 + 1];
#pragma unroll
            for (int ks = 0; ks < 4; ++ks) {
                uint32_t kh[4], kl[4];
                uint32_t a = st + kpat + j2 * (16 * 144) + ks * 32;
                ldsm_x4(kh, a + STG_KHI);
                ldsm_x4(kl, a + STG_KLO);
                mma_bf16(sA, qh[ks], kh[0], kh[1]);
                mma_bf16(sA, qh[ks], kl[0], kl[1]);
                mma_bf16(sA, ql[ks], kh[0], kh[1]);
                mma_bf16(sB, qh[ks], kh[2], kh[3]);
                mma_bf16(sB, qh[ks], kl[2], kl[3]);
                mma_bf16(sB, ql[ks], kh[2], kh[3]);
            }
        }

        // ---- exp (+ causal mask on diagonal tile) ----
        if (kb == qb) {
#pragma unroll
            for (int j = 0; j < 16; ++j) {
                int col = k0 + 8 * j + 2 * (lane & 3);
                float e0 = (col     <= ra)     ? __expf(s[j][0]) : 0.f;
                float e1 = (col + 1 <= ra)     ? __expf(s[j][1]) : 0.f;
                float e2 = (col     <= ra + 8) ? __expf(s[j][2]) : 0.f;
                float e3 = (col + 1 <= ra + 8) ? __expf(s[j][3]) : 0.f;
                s[j][0] = e0; s[j][1] = e1; s[j][2] = e2; s[j][3] = e3;
                l0 += e0 + e1; l1 += e2 + e3;
            }
        } else {
#pragma unroll
            for (int j = 0; j < 16; ++j) {
                float e0 = __expf(s[j][0]);
                float e1 = __expf(s[j][1]);
                float e2 = __expf(s[j][2]);
                float e3 = __expf(s[j][3]);
                s[j][0] = e0; s[j][1] = e1; s[j][2] = e2; s[j][3] = e3;
                l0 += e0 + e1; l1 += e2 + e3;
            }
        }

        // ---- O += P V ----
#pragma unroll
        for (int kc = 0; kc < 8; ++kc) {
            uint32_t ah[4], al[4];
#pragma unroll
            for (int half = 0; half < 2; ++half) {
                const float* sp = s[2 * kc + half];
                float h0 = __bfloat162float(__float2bfloat16(sp[0]));
                float h1 = __bfloat162float(__float2bfloat16(sp[1]));
                float h2 = __bfloat162float(__float2bfloat16(sp[2]));
                float h3 = __bfloat162float(__float2bfloat16(sp[3]));
                ah[2 * half + 0] = pack_bf16x2(sp[0], sp[1]);
                ah[2 * half + 1] = pack_bf16x2(sp[2], sp[3]);
                al[2 * half + 0] = pack_bf16x2(sp[0] - h0, sp[1] - h1);
                al[2 * half + 1] = pack_bf16x2(sp[2] - h2, sp[3] - h3);
            }
#pragma unroll
            for (int jp = 0; jp < 4; ++jp) {
                uint32_t vh[4], vl[4];
                uint32_t a = st + STG_VHI + vpat + jp * (16 * 272) + kc * 32;
                ldsm_x4(vh, a);
                ldsm_x4(vl, a + (STG_VLO - STG_VHI));
                mma_bf16(o[2 * jp],     ah, vh[0], vh[1]);
                mma_bf16(o[2 * jp],     al, vh[0], vh[1]);
                mma_bf16(o[2 * jp],     ah, vl[0], vl[1]);
                mma_bf16(o[2 * jp + 1], ah, vh[2], vh[3]);
                mma_bf16(o[2 * jp + 1], al, vh[2], vh[3]);
                mma_bf16(o[2 * jp + 1], ah, vl[2], vl[3]);
            }
        }

        if (it < 15) {
            if (changed) {
                flush(b, qb);
                load_q(nb, nqb);
                __syncthreads();
                build_q();
                zero_acc();
            }
            b = nb; qb = nqb; kb = nkb;
        }
    }
    flush(b, qb);
}

// ===========================================================================
// Kernel 3: normalize — out = O / l   (one float4 per thread, full chip)
// ===========================================================================
__global__ void norm_kernel(float* __restrict__ out)
{
    const int i = blockIdx.x * 256 + threadIdx.x;       // 262144 = NROWS*NH/4
    float4 v = reinterpret_cast<const float4*>(g_oacc)[i];
    float linv = 1.f / g_lacc[i >> 4];
    v.x *= linv; v.y *= linv; v.z *= linv; v.w *= linv;
    reinterpret_cast<float4*>(out)[i] = v;
}

// ===========================================================================
extern "C" void kernel_launch(void* const* d_in, const int* in_sizes, int n_in,
                              void* d_out, int out_size)
{
    (void)in_sizes; (void)n_in; (void)out_size;
    const float* x  = (const float*)d_in[0];
    const float* Wq = (const float*)d_in[1];
    const float* Wk = (const float*)d_in[2];
    const float* Wv = (const float*)d_in[3];
    float* out = (float*)d_out;

    cudaFuncSetAttribute(qkv_mma, cudaFuncAttributeMaxDynamicSharedMemorySize, QS_TOTAL);
    cudaFuncSetAttribute(attn_mma, cudaFuncAttributeMaxDynamicSharedMemorySize, SM_ATT_TOTAL);

    init_kernel<<<512, 256>>>(Wq, Wk, Wv);
    qkv_mma<<<128, 256, QS_TOTAL>>>(x);
    attn_mma<<<132, 256, SM_ATT_TOTAL>>>();
    norm_kernel<<<1024, 256>>>(out);
}

// round 9
// speedup vs baseline: 3.3841x; 1.0659x over previous
#include <cuda_runtime.h>
#include <cuda_bf16.h>
#include <cstdint>

#define NB 4
#define NT 4096
#define NC 1024
#define NH 64
#define NROWS (NB * NT)

// bf16 hi/lo split q, k (row-major [row][h]); v transposed ([b][h][t]).
__device__ __nv_bfloat16 g_qhi[NROWS * NH];
__device__ __nv_bfloat16 g_qlo[NROWS * NH];
__device__ __nv_bfloat16 g_khi[NROWS * NH];
__device__ __nv_bfloat16 g_klo[NROWS * NH];
__device__ __nv_bfloat16 g_vthi[NB * NH * NT];
__device__ __nv_bfloat16 g_vtlo[NB * NH * NT];
// W transposed bf16 hi/lo: [192 cols][1024 c]  (q:0-63, k:64-127, v:128-191)
__device__ __nv_bfloat16 g_wthi[192 * NC];
__device__ __nv_bfloat16 g_wtlo[192 * NC];
// split-K partial accumulators
__device__ float g_oacc[NROWS * NH];
__device__ float g_lacc[NROWS];

// ===========================================================================
// Helpers (sm_80-era PTX: ldmatrix / mma.sync / cp.async — OK in compute_100)
// ===========================================================================
__device__ __forceinline__ uint32_t smem_u32(const void* p) {
    uint32_t a;
    asm("{ .reg .u64 t; cvta.to.shared.u64 t, %1; cvt.u32.u64 %0, t; }"
        : "=r"(a) : "l"(p));
    return a;
}
__device__ __forceinline__ void ldsm_x4(uint32_t* r, uint32_t addr) {
    asm volatile("ldmatrix.sync.aligned.m8n8.x4.shared.b16 {%0,%1,%2,%3}, [%4];"
                 : "=r"(r[0]), "=r"(r[1]), "=r"(r[2]), "=r"(r[3]) : "r"(addr));
}
__device__ __forceinline__ void mma_bf16(float* c, const uint32_t* a,
                                         uint32_t b0, uint32_t b1) {
    asm volatile(
        "mma.sync.aligned.m16n8k16.row.col.f32.bf16.bf16.f32 "
        "{%0,%1,%2,%3}, {%4,%5,%6,%7}, {%8,%9}, {%0,%1,%2,%3};"
        : "+f"(c[0]), "+f"(c[1]), "+f"(c[2]), "+f"(c[3])
        : "r"(a[0]), "r"(a[1]), "r"(a[2]), "r"(a[3]), "r"(b0), "r"(b1));
}
__device__ __forceinline__ uint32_t pack_bf16x2(float lo, float hi) {
    uint32_t r;
    asm("cvt.rn.bf16x2.f32 %0, %1, %2;" : "=r"(r) : "f"(hi), "f"(lo));
    return r;
}
#define CP16(dst, src) \
    asm volatile("cp.async.cg.shared.global [%0], [%1], 16;" :: "r"(dst), "l"(src))
#define CP_COMMIT() asm volatile("cp.async.commit_group;" ::: "memory")
#define CP_WAIT0()  asm volatile("cp.async.wait_group 0;" ::: "memory")
#define CP_WAIT1()  asm volatile("cp.async.wait_group 1;" ::: "memory")

// ===========================================================================
// Kernel 0: init — zero split-K accumulators; build transposed bf16 hi/lo W.
// grid 512 x 256 threads = 131072
// ===========================================================================
__global__ void init_kernel(const float* __restrict__ Wq,
                            const float* __restrict__ Wk,
                            const float* __restrict__ Wv)
{
    const int tid = blockIdx.x * 256 + threadIdx.x;   // 0..131071
    float4 z = make_float4(0.f, 0.f, 0.f, 0.f);
#pragma unroll
    for (int i = tid; i < (NROWS * NH) / 4; i += 131072)
        reinterpret_cast<float4*>(g_oacc)[i] = z;
    if (tid < NROWS) g_lacc[tid] = 0.f;

    if (tid < 65536) {
        const int c = tid >> 6;      // 0..1023
        const int h = tid & 63;
        float wq = Wq[c * NH + h], wk = Wk[c * NH + h], wv = Wv[c * NH + h];
        __nv_bfloat16 h0 = __float2bfloat16(wq);
        __nv_bfloat16 h1 = __float2bfloat16(wk);
        __nv_bfloat16 h2 = __float2bfloat16(wv);
        g_wthi[(h)       * NC + c] = h0;
        g_wthi[(64 + h)  * NC + c] = h1;
        g_wthi[(128 + h) * NC + c] = h2;
        g_wtlo[(h)       * NC + c] = __float2bfloat16(wq - __bfloat162float(h0));
        g_wtlo[(64 + h)  * NC + c] = __float2bfloat16(wk - __bfloat162float(h1));
        g_wtlo[(128 + h) * NC + c] = __float2bfloat16(wv - __bfloat162float(h2));
    }
}

// ===========================================================================
// Kernel 1: QKV projection via mma.sync bf16 3-term split (unchanged from R8).
// ===========================================================================
#define QS_XHI 0
#define QS_XLO 18432
#define QS_W   36864
#define QS_WSTG 55296
#define QS_TOTAL (QS_W + 2 * QS_WSTG)  // 147456 B

__global__ __launch_bounds__(256, 1)
void qkv_mma(const float* __restrict__ x)
{
    extern __shared__ char smem[];
    const uint32_t sb = smem_u32(smem);
    const int t    = threadIdx.x;
    const int w    = t >> 5;
    const int lane = t & 31;
    const int row0 = blockIdx.x * 128;

    float acc[24][4];
#pragma unroll
    for (int j = 0; j < 24; ++j)
#pragma unroll
        for (int c = 0; c < 4; ++c) acc[j][c] = 0.f;

    const uint32_t apat = (w * 16 + (lane & 15)) * 144 + (lane >> 4) * 16;
    const uint32_t bpat = ((((lane >> 4) << 3) + (lane & 7)) * 144) +
                          ((lane >> 3) & 1) * 16;

    float4 xreg[8];
    auto load_x = [&](int c0) {
#pragma unroll
        for (int it = 0; it < 8; ++it) {
            int i   = t + it * 256;
            int row = i >> 4;
            int c4  = (i & 15) * 4;
            xreg[it] = *reinterpret_cast<const float4*>(
                x + (size_t)(row0 + row) * NC + c0 + c4);
        }
    };
    auto store_x = [&]() {
#pragma unroll
        for (int it = 0; it < 8; ++it) {
            int i   = t + it * 256;
            int row = i >> 4;
            int c4  = (i & 15) * 4;
            float4 v = xreg[it];
            float hx = __bfloat162float(__float2bfloat16(v.x));
            float hy = __bfloat162float(__float2bfloat16(v.y));
            float hz = __bfloat162float(__float2bfloat16(v.z));
            float hw = __bfloat162float(__float2bfloat16(v.w));
            uint2 hi2 = make_uint2(pack_bf16x2(v.x, v.y), pack_bf16x2(v.z, v.w));
            uint2 lo2 = make_uint2(pack_bf16x2(v.x - hx, v.y - hy),
                                   pack_bf16x2(v.z - hz, v.w - hw));
            uint32_t doff = row * 144 + c4 * 2;
            *reinterpret_cast<uint2*>(smem + QS_XHI + doff) = hi2;
            *reinterpret_cast<uint2*>(smem + QS_XLO + doff) = lo2;
        }
    };
    auto issue_w = [&](int stage, int c0) {
        uint32_t st = sb + QS_W + stage * QS_WSTG;
#pragma unroll
        for (int it = 0; it < 6; ++it) {
            int i   = t + it * 256;
            int col = i >> 3;
            int c8  = (i & 7) * 8;
            uint32_t doff = col * 144 + c8 * 2;
            CP16(st + doff,         g_wthi + (size_t)col * NC + c0 + c8);
            CP16(st + 27648 + doff, g_wtlo + (size_t)col * NC + c0 + c8);
        }
    };

    issue_w(0, 0);
    CP_COMMIT();
    load_x(0);

    for (int c = 0; c < 16; ++c) {
        const int c0 = c * 64;
        __syncthreads();
        if (c < 15) { issue_w((c + 1) & 1, c0 + 64); CP_COMMIT(); }
        store_x();
        if (c < 15) load_x(c0 + 64);
        if (c < 15) { CP_WAIT1(); } else { CP_WAIT0(); }
        __syncthreads();

        const uint32_t wst = sb + QS_W + (c & 1) * QS_WSTG;
        uint32_t ah[4][4], al[4][4];
#pragma unroll
        for (int ks = 0; ks < 4; ++ks) {
            ldsm_x4(ah[ks], sb + QS_XHI + apat + ks * 32);
            ldsm_x4(al[ks], sb + QS_XLO + apat + ks * 32);
        }
#pragma unroll
        for (int n2 = 0; n2 < 12; ++n2) {
            float* cA = acc[2 * n2];
            float* cB = acc[2 * n2 + 1];
#pragma unroll
            for (int ks = 0; ks < 4; ++ks) {
                uint32_t bh[4], bl[4];
                uint32_t a = wst + bpat + n2 * (16 * 144) + ks * 32;
                ldsm_x4(bh, a);
                ldsm_x4(bl, a + 27648);
                mma_bf16(cA, ah[ks], bh[0], bh[1]);
                mma_bf16(cA, ah[ks], bl[0], bl[1]);
                mma_bf16(cA, al[ks], bh[0], bh[1]);
                mma_bf16(cB, ah[ks], bh[2], bh[3]);
                mma_bf16(cB, ah[ks], bl[2], bl[3]);
                mma_bf16(cB, al[ks], bh[2], bh[3]);
            }
        }
    }

    const int ra = row0 + w * 16 + (lane >> 2);
#pragma unroll
    for (int j = 0; j < 24; ++j) {
        int col = 8 * j + 2 * (lane & 3);
#pragma unroll
        for (int half = 0; half < 2; ++half) {
            int row = ra + 8 * half;
            float v0 = acc[j][2 * half], v1 = acc[j][2 * half + 1];
            float h0 = __bfloat162float(__float2bfloat16(v0));
            float h1 = __bfloat162float(__float2bfloat16(v1));
            uint32_t hi = pack_bf16x2(v0, v1);
            uint32_t lo = pack_bf16x2(v0 - h0, v1 - h1);
            if (col < 64) {
                *reinterpret_cast<uint32_t*>(g_qhi + (size_t)row * NH + col) = hi;
                *reinterpret_cast<uint32_t*>(g_qlo + (size_t)row * NH + col) = lo;
            } else if (col < 128) {
                *reinterpret_cast<uint32_t*>(g_khi + (size_t)row * NH + col - 64) = hi;
                *reinterpret_cast<uint32_t*>(g_klo + (size_t)row * NH + col - 64) = lo;
            } else {
                int h  = col - 128;
                int bb = row >> 12, tt = row & (NT - 1);
                size_t i0 = ((size_t)bb * NH + h) * NT + tt;
                g_vthi[i0]      = __float2bfloat16(v0);
                g_vtlo[i0]      = __float2bfloat16(v0 - h0);
                g_vthi[i0 + NT] = __float2bfloat16(v1);
                g_vtlo[i0 + NT] = __float2bfloat16(v1 - h1);
            }
        }
    }
}

// ===========================================================================
// Kernel 2: balanced split-K causal attention, 2 CTAs/SM.
// 128 threads (4 warps), tile = 64 q-rows x 128 keys. Single cp.async K/V
// stage (90112 B/CTA -> two CTAs co-resident; cross-CTA overlap hides loads
// and the exp/pack phases). 4224 tiles over 296 blocks (80x15 + 216x14).
// ===========================================================================
#define STG_KHI 0
#define STG_KLO 18432
#define STG_VHI 36864
#define STG_VLO 54272
#define STG_SZ  71680
#define SM_Q_HI STG_SZ                  // 71680
#define SM_Q_LO (SM_Q_HI + 9216)
#define SM_ATT_TOTAL (SM_Q_LO + 9216)   // 90112 B

__global__ __launch_bounds__(128, 2)
void attn_mma()
{
    extern __shared__ char smem[];
    const uint32_t sb = smem_u32(smem);
    const int t    = threadIdx.x;
    const int w    = t >> 5;          // 0..3
    const int lane = t & 31;

    // ---- linear tile range for this block ----
    const int bid = blockIdx.x;
    int g0  = bid * 14 + (bid < 80 ? bid : 80);
    int cnt = 14 + (bid < 80 ? 1 : 0);

    // decode (b, qi, kb): per-b tiles = 1056; q-tiles are 64 rows; k-tiles 128.
    int b = g0 / 1056;
    int r = g0 % 1056;
    int qi = 0, cum = 0;
    while (cum + (qi >> 1) + 1 <= r) { cum += (qi >> 1) + 1; ++qi; }
    int kb = r - cum;

    const uint32_t kpat = ((((lane >> 4) << 3) + (lane & 7)) * 144) +
                          ((lane >> 3) & 1) * 16;
    const uint32_t vpat = ((((lane >> 4) << 3) + (lane & 7)) * 272) +
                          ((lane >> 3) & 1) * 16;
    const uint32_t qpat = (w * 16 + (lane & 15)) * 144 + (lane >> 4) * 16;

    auto issue_kv = [&](int bb, int kbb) {
        int k0 = kbb * 128;
        const __nv_bfloat16* kh = g_khi + ((size_t)bb * NT + k0) * NH;
        const __nv_bfloat16* kl = g_klo + ((size_t)bb * NT + k0) * NH;
#pragma unroll
        for (int it = 0; it < 8; ++it) {
            int i   = t + it * 128;        // 0..1023
            int row = i >> 3;
            int c8  = (i & 7) * 8;
            uint32_t doff = row * 144 + c8 * 2;
            CP16(sb + STG_KHI + doff, kh + row * NH + c8);
            CP16(sb + STG_KLO + doff, kl + row * NH + c8);
        }
        const __nv_bfloat16* vh = g_vthi + (size_t)bb * NH * NT + k0;
        const __nv_bfloat16* vl = g_vtlo + (size_t)bb * NH * NT + k0;
#pragma unroll
        for (int it = 0; it < 8; ++it) {
            int i  = t + it * 128;
            int h  = i >> 4;               // 0..63
            int k8 = (i & 15) * 8;
            uint32_t doff = h * 272 + k8 * 2;
            CP16(sb + STG_VHI + doff, vh + (size_t)h * NT + k8);
            CP16(sb + STG_VLO + doff, vl + (size_t)h * NT + k8);
        }
    };
    auto load_q = [&](int bb, int qii) {
        const __nv_bfloat16* qh = g_qhi + ((size_t)bb * NT + qii * 64) * NH;
        const __nv_bfloat16* ql = g_qlo + ((size_t)bb * NT + qii * 64) * NH;
#pragma unroll
        for (int it = 0; it < 4; ++it) {
            int i   = t + it * 128;        // 0..511
            int row = i >> 3;              // 0..63
            int c8  = (i & 7) * 8;
            uint32_t doff = row * 144 + c8 * 2;
            *reinterpret_cast<uint4*>(smem + SM_Q_HI + doff) =
                *reinterpret_cast<const uint4*>(qh + row * NH + c8);
            *reinterpret_cast<uint4*>(smem + SM_Q_LO + doff) =
                *reinterpret_cast<const uint4*>(ql + row * NH + c8);
        }
    };

    uint32_t qh[4][4], ql[4][4];
    auto build_q = [&]() {
#pragma unroll
        for (int ks = 0; ks < 4; ++ks) {
            ldsm_x4(qh[ks], sb + SM_Q_HI + qpat + ks * 32);
            ldsm_x4(ql[ks], sb + SM_Q_LO + qpat + ks * 32);
        }
    };

    float o[8][4], l0, l1;
    auto zero_acc = [&]() {
#pragma unroll
        for (int j = 0; j < 8; ++j)
#pragma unroll
            for (int c = 0; c < 4; ++c) o[j][c] = 0.f;
        l0 = l1 = 0.f;
    };
    auto flush = [&](int bb, int qii) {
        float r0 = l0, r1 = l1;
        r0 += __shfl_xor_sync(0xffffffffu, r0, 1);
        r0 += __shfl_xor_sync(0xffffffffu, r0, 2);
        r1 += __shfl_xor_sync(0xffffffffu, r1, 1);
        r1 += __shfl_xor_sync(0xffffffffu, r1, 2);
        int rra = bb * NT + qii * 64 + w * 16 + (lane >> 2);
        if ((lane & 3) == 0) {
            atomicAdd(&g_lacc[rra], r0);
            atomicAdd(&g_lacc[rra + 8], r1);
        }
        float* o0 = g_oacc + (size_t)rra * NH;
        float* o1 = g_oacc + (size_t)(rra + 8) * NH;
#pragma unroll
        for (int j = 0; j < 8; ++j) {
            int h = 8 * j + 2 * (lane & 3);
            atomicAdd(o0 + h,     o[j][0]);
            atomicAdd(o0 + h + 1, o[j][1]);
            atomicAdd(o1 + h,     o[j][2]);
            atomicAdd(o1 + h + 1, o[j][3]);
        }
    };

    // ---- prologue ----
    issue_kv(b, kb);
    CP_COMMIT();
    load_q(b, qi);
    __syncthreads();
    build_q();
    zero_acc();

    for (int it = 0; it < cnt; ++it) {
        CP_WAIT0();
        __syncthreads();                   // stage data visible to all warps

        const int k0 = kb * 128;
        const int ra = qi * 64 + w * 16 + (lane >> 2);
        const bool diag = (kb == (qi >> 1));

        // ---- S = Q K^T ----
        float s[16][4];
#pragma unroll
        for (int j = 0; j < 16; ++j)
#pragma unroll
            for (int c = 0; c < 4; ++c) s[j][c] = 0.f;
#pragma unroll
        for (int j2 = 0; j2 < 8; ++j2) {
            float* sA = s[2 * j2];
            float* sB = s[2 * j2 + 1];
#pragma unroll
            for (int ks = 0; ks < 4; ++ks) {
                uint32_t kh[4], kl[4];
                uint32_t a = sb + kpat + j2 * (16 * 144) + ks * 32;
                ldsm_x4(kh, a + STG_KHI);
                ldsm_x4(kl, a + STG_KLO);
                mma_bf16(sA, qh[ks], kh[0], kh[1]);
                mma_bf16(sA, qh[ks], kl[0], kl[1]);
                mma_bf16(sA, ql[ks], kh[0], kh[1]);
                mma_bf16(sB, qh[ks], kh[2], kh[3]);
                mma_bf16(sB, qh[ks], kl[2], kl[3]);
                mma_bf16(sB, ql[ks], kh[2], kh[3]);
            }
        }

        // ---- exp (+ causal mask on diagonal tile) ----
        if (diag) {
#pragma unroll
            for (int j = 0; j < 16; ++j) {
                int col = k0 + 8 * j + 2 * (lane & 3);
                float e0 = (col     <= ra)     ? __expf(s[j][0]) : 0.f;
                float e1 = (col + 1 <= ra)     ? __expf(s[j][1]) : 0.f;
                float e2 = (col     <= ra + 8) ? __expf(s[j][2]) : 0.f;
                float e3 = (col + 1 <= ra + 8) ? __expf(s[j][3]) : 0.f;
                s[j][0] = e0; s[j][1] = e1; s[j][2] = e2; s[j][3] = e3;
                l0 += e0 + e1; l1 += e2 + e3;
            }
        } else {
#pragma unroll
            for (int j = 0; j < 16; ++j) {
                float e0 = __expf(s[j][0]);
                float e1 = __expf(s[j][1]);
                float e2 = __expf(s[j][2]);
                float e3 = __expf(s[j][3]);
                s[j][0] = e0; s[j][1] = e1; s[j][2] = e2; s[j][3] = e3;
                l0 += e0 + e1; l1 += e2 + e3;
            }
        }

        // ---- O += P V ----
#pragma unroll
        for (int kc = 0; kc < 8; ++kc) {
            uint32_t ah[4], al[4];
#pragma unroll
            for (int half = 0; half < 2; ++half) {
                const float* sp = s[2 * kc + half];
                float h0 = __bfloat162float(__float2bfloat16(sp[0]));
                float h1 = __bfloat162float(__float2bfloat16(sp[1]));
                float h2 = __bfloat162float(__float2bfloat16(sp[2]));
                float h3 = __bfloat162float(__float2bfloat16(sp[3]));
                ah[2 * half + 0] = pack_bf16x2(sp[0], sp[1]);
                ah[2 * half + 1] = pack_bf16x2(sp[2], sp[3]);
                al[2 * half + 0] = pack_bf16x2(sp[0] - h0, sp[1] - h1);
                al[2 * half + 1] = pack_bf16x2(sp[2] - h2, sp[3] - h3);
            }
#pragma unroll
            for (int jp = 0; jp < 4; ++jp) {
                uint32_t vh[4], vl[4];
                uint32_t a = sb + STG_VHI + vpat + jp * (16 * 272) + kc * 32;
                ldsm_x4(vh, a);
                ldsm_x4(vl, a + (STG_VLO - STG_VHI));
                mma_bf16(o[2 * jp],     ah, vh[0], vh[1]);
                mma_bf16(o[2 * jp],     al, vh[0], vh[1]);
                mma_bf16(o[2 * jp],     ah, vl[0], vl[1]);
                mma_bf16(o[2 * jp + 1], ah, vh[2], vh[3]);
                mma_bf16(o[2 * jp + 1], al, vh[2], vh[3]);
                mma_bf16(o[2 * jp + 1], ah, vl[2], vl[3]);
            }
        }

        // ---- advance; refill stage; flush on q-tile change ----
        int nb = b, nqi = qi, nkb = kb + 1;
        bool changed = false;
        if (nkb > (qi >> 1)) {
            nkb = 0; ++nqi; changed = true;
            if (nqi == 64) { nqi = 0; ++nb; }
        }

        __syncthreads();                   // all warps done reading stage
        if (it < cnt - 1) { issue_kv(nb, nkb); CP_COMMIT(); }
        if (it < cnt - 1 && changed) {
            flush(b, qi);
            load_q(nb, nqi);
            __syncthreads();
            build_q();
            zero_acc();
        }
        b = nb; qi = nqi; kb = nkb;
    }
    // loop exits with (b,qi,kb) already advanced; flush the LAST computed tile
    // indices: recover them — the final compute used pre-advance values, which
    // flush() needs. Track via saved copies:
    // (handled by flushing before advance on the final iteration below)
    // NOTE: since advance happened, recompute previous q-tile:
    {
        int pb = b, pqi = qi;
        if (kb == 0) {                     // we just wrapped a q-tile
            if (pqi == 0) { --pb; pqi = 64; }
            --pqi;
        }
        flush(pb, pqi);
    }
}

// ===========================================================================
// Kernel 3: normalize — out = O / l   (one float4 per thread, full chip)
// ===========================================================================
__global__ void norm_kernel(float* __restrict__ out)
{
    const int i = blockIdx.x * 256 + threadIdx.x;       // 262144 = NROWS*NH/4
    float4 v = reinterpret_cast<const float4*>(g_oacc)[i];
    float linv = 1.f / g_lacc[i >> 4];
    v.x *= linv; v.y *= linv; v.z *= linv; v.w *= linv;
    reinterpret_cast<float4*>(out)[i] = v;
}

// ===========================================================================
extern "C" void kernel_launch(void* const* d_in, const int* in_sizes, int n_in,
                              void* d_out, int out_size)
{
    (void)in_sizes; (void)n_in; (void)out_size;
    const float* x  = (const float*)d_in[0];
    const float* Wq = (const float*)d_in[1];
    const float* Wk = (const float*)d_in[2];
    const float* Wv = (const float*)d_in[3];
    float* out = (float*)d_out;

    cudaFuncSetAttribute(qkv_mma, cudaFuncAttributeMaxDynamicSharedMemorySize, QS_TOTAL);
    cudaFuncSetAttribute(attn_mma, cudaFuncAttributeMaxDynamicSharedMemorySize, SM_ATT_TOTAL);

    init_kernel<<<512, 256>>>(Wq, Wk, Wv);
    qkv_mma<<<128, 256, QS_TOTAL>>>(x);
    attn_mma<<<296, 128, SM_ATT_TOTAL>>>();
    norm_kernel<<<1024, 256>>>(out);
}

// round 10
// speedup vs baseline: 3.4277x; 1.0129x over previous
#include <cuda_runtime.h>
#include <cuda_bf16.h>
#include <cstdint>

#define NB 4
#define NT 4096
#define NC 1024
#define NH 64
#define NROWS (NB * NT)

// bf16 hi/lo split q, k (row-major [row][h]); v transposed ([b][h][t]).
__device__ __nv_bfloat16 g_qhi[NROWS * NH];
__device__ __nv_bfloat16 g_qlo[NROWS * NH];
__device__ __nv_bfloat16 g_khi[NROWS * NH];
__device__ __nv_bfloat16 g_klo[NROWS * NH];
__device__ __nv_bfloat16 g_vthi[NB * NH * NT];
__device__ __nv_bfloat16 g_vtlo[NB * NH * NT];
// W transposed bf16 hi/lo: [192 cols][1024 c]  (q:0-63, k:64-127, v:128-191)
__device__ __nv_bfloat16 g_wthi[192 * NC];
__device__ __nv_bfloat16 g_wtlo[192 * NC];
// split-K partial accumulators
__device__ float g_oacc[NROWS * NH];
__device__ float g_lacc[NROWS];

// ===========================================================================
// Helpers (sm_80-era PTX: ldmatrix / mma.sync / cp.async — OK in compute_100)
// ===========================================================================
__device__ __forceinline__ uint32_t smem_u32(const void* p) {
    uint32_t a;
    asm("{ .reg .u64 t; cvta.to.shared.u64 t, %1; cvt.u32.u64 %0, t; }"
        : "=r"(a) : "l"(p));
    return a;
}
__device__ __forceinline__ void ldsm_x4(uint32_t* r, uint32_t addr) {
    asm volatile("ldmatrix.sync.aligned.m8n8.x4.shared.b16 {%0,%1,%2,%3}, [%4];"
                 : "=r"(r[0]), "=r"(r[1]), "=r"(r[2]), "=r"(r[3]) : "r"(addr));
}
__device__ __forceinline__ void mma_bf16(float* c, const uint32_t* a,
                                         uint32_t b0, uint32_t b1) {
    asm volatile(
        "mma.sync.aligned.m16n8k16.row.col.f32.bf16.bf16.f32 "
        "{%0,%1,%2,%3}, {%4,%5,%6,%7}, {%8,%9}, {%0,%1,%2,%3};"
        : "+f"(c[0]), "+f"(c[1]), "+f"(c[2]), "+f"(c[3])
        : "r"(a[0]), "r"(a[1]), "r"(a[2]), "r"(a[3]), "r"(b0), "r"(b1));
}
__device__ __forceinline__ uint32_t pack_bf16x2(float lo, float hi) {
    uint32_t r;
    asm("cvt.rn.bf16x2.f32 %0, %1, %2;" : "=r"(r) : "f"(hi), "f"(lo));
    return r;
}
#define CP16(dst, src) \
    asm volatile("cp.async.cg.shared.global [%0], [%1], 16;" :: "r"(dst), "l"(src))
#define CP_COMMIT() asm volatile("cp.async.commit_group;" ::: "memory")
#define CP_WAIT0()  asm volatile("cp.async.wait_group 0;" ::: "memory")
#define CP_WAIT1()  asm volatile("cp.async.wait_group 1;" ::: "memory")

// ===========================================================================
// Kernel 0: init — zero split-K accumulators; build transposed bf16 hi/lo W.
// ===========================================================================
__global__ void init_kernel(const float* __restrict__ Wq,
                            const float* __restrict__ Wk,
                            const float* __restrict__ Wv)
{
    const int tid = blockIdx.x * 256 + threadIdx.x;   // 0..131071
    float4 z = make_float4(0.f, 0.f, 0.f, 0.f);
#pragma unroll
    for (int i = tid; i < (NROWS * NH) / 4; i += 131072)
        reinterpret_cast<float4*>(g_oacc)[i] = z;
    if (tid < NROWS) g_lacc[tid] = 0.f;

    if (tid < 65536) {
        const int c = tid >> 6;      // 0..1023
        const int h = tid & 63;
        float wq = Wq[c * NH + h], wk = Wk[c * NH + h], wv = Wv[c * NH + h];
        __nv_bfloat16 h0 = __float2bfloat16(wq);
        __nv_bfloat16 h1 = __float2bfloat16(wk);
        __nv_bfloat16 h2 = __float2bfloat16(wv);
        g_wthi[(h)       * NC + c] = h0;
        g_wthi[(64 + h)  * NC + c] = h1;
        g_wthi[(128 + h) * NC + c] = h2;
        g_wtlo[(h)       * NC + c] = __float2bfloat16(wq - __bfloat162float(h0));
        g_wtlo[(64 + h)  * NC + c] = __float2bfloat16(wk - __bfloat162float(h1));
        g_wtlo[(128 + h) * NC + c] = __float2bfloat16(wv - __bfloat162float(h2));
    }
}

// ===========================================================================
// Kernel 1: QKV projection via mma.sync bf16 3-term split.
// 128 blocks x 128 rows, 256 threads. Double-buffered X (convert/store moved
// off the inter-barrier critical path) + double-buffered cp.async W stages.
// ===========================================================================
#define QS_XSTG 36864                  // per X stage: hi 18432 + lo 18432
#define QS_W    73728
#define QS_WSTG 55296                  // hi 27648 + lo 27648
#define QS_TOTAL (QS_W + 2 * QS_WSTG)  // 184320 B

__global__ __launch_bounds__(256, 1)
void qkv_mma(const float* __restrict__ x)
{
    extern __shared__ char smem[];
    const uint32_t sb = smem_u32(smem);
    const int t    = threadIdx.x;
    const int w    = t >> 5;
    const int lane = t & 31;
    const int row0 = blockIdx.x * 128;

    float acc[24][4];
#pragma unroll
    for (int j = 0; j < 24; ++j)
#pragma unroll
        for (int c = 0; c < 4; ++c) acc[j][c] = 0.f;

    const uint32_t apat = (w * 16 + (lane & 15)) * 144 + (lane >> 4) * 16;
    const uint32_t bpat = ((((lane >> 4) << 3) + (lane & 7)) * 144) +
                          ((lane >> 3) & 1) * 16;

    float4 xreg[8];
    auto load_x = [&](int c0) {
#pragma unroll
        for (int it = 0; it < 8; ++it) {
            int i   = t + it * 256;
            int row = i >> 4;
            int c4  = (i & 15) * 4;
            xreg[it] = *reinterpret_cast<const float4*>(
                x + (size_t)(row0 + row) * NC + c0 + c4);
        }
    };
    auto store_x = [&](int stage) {
        char* xb = smem + stage * QS_XSTG;
#pragma unroll
        for (int it = 0; it < 8; ++it) {
            int i   = t + it * 256;
            int row = i >> 4;
            int c4  = (i & 15) * 4;
            float4 v = xreg[it];
            float hx = __bfloat162float(__float2bfloat16(v.x));
            float hy = __bfloat162float(__float2bfloat16(v.y));
            float hz = __bfloat162float(__float2bfloat16(v.z));
            float hw = __bfloat162float(__float2bfloat16(v.w));
            uint2 hi2 = make_uint2(pack_bf16x2(v.x, v.y), pack_bf16x2(v.z, v.w));
            uint2 lo2 = make_uint2(pack_bf16x2(v.x - hx, v.y - hy),
                                   pack_bf16x2(v.z - hz, v.w - hw));
            uint32_t doff = row * 144 + c4 * 2;
            *reinterpret_cast<uint2*>(xb + doff)         = hi2;
            *reinterpret_cast<uint2*>(xb + 18432 + doff) = lo2;
        }
    };
    auto issue_w = [&](int stage, int c0) {
        uint32_t st = sb + QS_W + stage * QS_WSTG;
#pragma unroll
        for (int it = 0; it < 6; ++it) {
            int i   = t + it * 256;
            int col = i >> 3;
            int c8  = (i & 7) * 8;
            uint32_t doff = col * 144 + c8 * 2;
            CP16(st + doff,         g_wthi + (size_t)col * NC + c0 + c8);
            CP16(st + 27648 + doff, g_wtlo + (size_t)col * NC + c0 + c8);
        }
    };

    // prologue: W0 in flight; chunk 0 converted into X0; chunk 1 in regs.
    issue_w(0, 0);
    CP_COMMIT();
    load_x(0);
    store_x(0);
    load_x(64);

    for (int c = 0; c < 16; ++c) {
        __syncthreads();               // MMA c-1 done everywhere:
                                       // frees W stage (c+1)&1 and X[(c+1)&1]
        if (c < 15) { issue_w((c + 1) & 1, (c + 1) * 64); CP_COMMIT(); }
        if (c < 15) { CP_WAIT1(); } else { CP_WAIT0(); }
        __syncthreads();               // W_c + X[c&1] visible to all warps

        const uint32_t xst = sb + (c & 1) * QS_XSTG;
        const uint32_t wst = sb + QS_W + (c & 1) * QS_WSTG;
        uint32_t ah[4][4], al[4][4];
#pragma unroll
        for (int ks = 0; ks < 4; ++ks) {
            ldsm_x4(ah[ks], xst + apat + ks * 32);
            ldsm_x4(al[ks], xst + 18432 + apat + ks * 32);
        }
#pragma unroll
        for (int n2 = 0; n2 < 12; ++n2) {
            float* cA = acc[2 * n2];
            float* cB = acc[2 * n2 + 1];
#pragma unroll
            for (int ks = 0; ks < 4; ++ks) {
                uint32_t bh[4], bl[4];
                uint32_t a = wst + bpat + n2 * (16 * 144) + ks * 32;
                ldsm_x4(bh, a);
                ldsm_x4(bl, a + 27648);
                mma_bf16(cA, ah[ks], bh[0], bh[1]);
                mma_bf16(cA, ah[ks], bl[0], bl[1]);
                mma_bf16(cA, al[ks], bh[0], bh[1]);
                mma_bf16(cB, ah[ks], bh[2], bh[3]);
                mma_bf16(cB, ah[ks], bl[2], bl[3]);
                mma_bf16(cB, al[ks], bh[2], bh[3]);
            }
        }
        // post-MMA: convert/store NEXT chunk (X[(c+1)&1] is free — last read by
        // MMA c-1, proven done by this phase's first barrier), prefetch c+2.
        if (c < 15) {
            store_x((c + 1) & 1);
            if (c < 14) load_x((c + 2) * 64);
        }
    }

    const int ra = row0 + w * 16 + (lane >> 2);
#pragma unroll
    for (int j = 0; j < 24; ++j) {
        int col = 8 * j + 2 * (lane & 3);
#pragma unroll
        for (int half = 0; half < 2; ++half) {
            int row = ra + 8 * half;
            float v0 = acc[j][2 * half], v1 = acc[j][2 * half + 1];
            float h0 = __bfloat162float(__float2bfloat16(v0));
            float h1 = __bfloat162float(__float2bfloat16(v1));
            uint32_t hi = pack_bf16x2(v0, v1);
            uint32_t lo = pack_bf16x2(v0 - h0, v1 - h1);
            if (col < 64) {
                *reinterpret_cast<uint32_t*>(g_qhi + (size_t)row * NH + col) = hi;
                *reinterpret_cast<uint32_t*>(g_qlo + (size_t)row * NH + col) = lo;
            } else if (col < 128) {
                *reinterpret_cast<uint32_t*>(g_khi + (size_t)row * NH + col - 64) = hi;
                *reinterpret_cast<uint32_t*>(g_klo + (size_t)row * NH + col - 64) = lo;
            } else {
                int h  = col - 128;
                int bb = row >> 12, tt = row & (NT - 1);
                size_t i0 = ((size_t)bb * NH + h) * NT + tt;
                g_vthi[i0]      = __float2bfloat16(v0);
                g_vtlo[i0]      = __float2bfloat16(v0 - h0);
                g_vthi[i0 + NT] = __float2bfloat16(v1);
                g_vtlo[i0 + NT] = __float2bfloat16(v1 - h1);
            }
        }
    }
}

// ===========================================================================
// Kernel 2: balanced split-K causal attention, 2 CTAs/SM, split-wait K/V
// pipeline: K and V are separate cp.async groups; next K is issued right
// after S (overlapping exp+PV), next V right after PV (overlapping next S).
// ===========================================================================
#define STG_KHI 0
#define STG_KLO 18432
#define STG_VHI 36864
#define STG_VLO 54272
#define STG_SZ  71680
#define SM_Q_HI STG_SZ                  // 71680
#define SM_Q_LO (SM_Q_HI + 9216)
#define SM_ATT_TOTAL (SM_Q_LO + 9216)   // 90112 B

__global__ __launch_bounds__(128, 2)
void attn_mma()
{
    extern __shared__ char smem[];
    const uint32_t sb = smem_u32(smem);
    const int t    = threadIdx.x;
    const int w    = t >> 5;          // 0..3
    const int lane = t & 31;

    // ---- linear tile range for this block ----
    const int bid = blockIdx.x;
    int g0  = bid * 14 + (bid < 80 ? bid : 80);
    int cnt = 14 + (bid < 80 ? 1 : 0);

    int b = g0 / 1056;
    int r = g0 % 1056;
    int qi = 0, cum = 0;
    while (cum + (qi >> 1) + 1 <= r) { cum += (qi >> 1) + 1; ++qi; }
    int kb = r - cum;

    const uint32_t kpat = ((((lane >> 4) << 3) + (lane & 7)) * 144) +
                          ((lane >> 3) & 1) * 16;
    const uint32_t vpat = ((((lane >> 4) << 3) + (lane & 7)) * 272) +
                          ((lane >> 3) & 1) * 16;
    const uint32_t qpat = (w * 16 + (lane & 15)) * 144 + (lane >> 4) * 16;

    auto issue_k = [&](int bb, int kbb) {
        int k0 = kbb * 128;
        const __nv_bfloat16* kh = g_khi + ((size_t)bb * NT + k0) * NH;
        const __nv_bfloat16* kl = g_klo + ((size_t)bb * NT + k0) * NH;
#pragma unroll
        for (int it = 0; it < 8; ++it) {
            int i   = t + it * 128;        // 0..1023
            int row = i >> 3;
            int c8  = (i & 7) * 8;
            uint32_t doff = row * 144 + c8 * 2;
            CP16(sb + STG_KHI + doff, kh + row * NH + c8);
            CP16(sb + STG_KLO + doff, kl + row * NH + c8);
        }
    };
    auto issue_v = [&](int bb, int kbb) {
        int k0 = kbb * 128;
        const __nv_bfloat16* vh = g_vthi + (size_t)bb * NH * NT + k0;
        const __nv_bfloat16* vl = g_vtlo + (size_t)bb * NH * NT + k0;
#pragma unroll
        for (int it = 0; it < 8; ++it) {
            int i  = t + it * 128;
            int h  = i >> 4;               // 0..63
            int k8 = (i & 15) * 8;
            uint32_t doff = h * 272 + k8 * 2;
            CP16(sb + STG_VHI + doff, vh + (size_t)h * NT + k8);
            CP16(sb + STG_VLO + doff, vl + (size_t)h * NT + k8);
        }
    };
    auto load_q = [&](int bb, int qii) {
        const __nv_bfloat16* qh = g_qhi + ((size_t)bb * NT + qii * 64) * NH;
        const __nv_bfloat16* ql = g_qlo + ((size_t)bb * NT + qii * 64) * NH;
#pragma unroll
        for (int it = 0; it < 4; ++it) {
            int i   = t + it * 128;        // 0..511
            int row = i >> 3;              // 0..63
            int c8  = (i & 7) * 8;
            uint32_t doff = row * 144 + c8 * 2;
            *reinterpret_cast<uint4*>(smem + SM_Q_HI + doff) =
                *reinterpret_cast<const uint4*>(qh + row * NH + c8);
            *reinterpret_cast<uint4*>(smem + SM_Q_LO + doff) =
                *reinterpret_cast<const uint4*>(ql + row * NH + c8);
        }
    };

    uint32_t qh[4][4], ql[4][4];
    auto build_q = [&]() {
#pragma unroll
        for (int ks = 0; ks < 4; ++ks) {
            ldsm_x4(qh[ks], sb + SM_Q_HI + qpat + ks * 32);
            ldsm_x4(ql[ks], sb + SM_Q_LO + qpat + ks * 32);
        }
    };

    float o[8][4], l0, l1;
    auto zero_acc = [&]() {
#pragma unroll
        for (int j = 0; j < 8; ++j)
#pragma unroll
            for (int c = 0; c < 4; ++c) o[j][c] = 0.f;
        l0 = l1 = 0.f;
    };
    auto flush = [&](int bb, int qii) {
        float r0 = l0, r1 = l1;
        r0 += __shfl_xor_sync(0xffffffffu, r0, 1);
        r0 += __shfl_xor_sync(0xffffffffu, r0, 2);
        r1 += __shfl_xor_sync(0xffffffffu, r1, 1);
        r1 += __shfl_xor_sync(0xffffffffu, r1, 2);
        int rra = bb * NT + qii * 64 + w * 16 + (lane >> 2);
        if ((lane & 3) == 0) {
            atomicAdd(&g_lacc[rra], r0);
            atomicAdd(&g_lacc[rra + 8], r1);
        }
        float* o0 = g_oacc + (size_t)rra * NH;
        float* o1 = g_oacc + (size_t)(rra + 8) * NH;
#pragma unroll
        for (int j = 0; j < 8; ++j) {
            int h = 8 * j + 2 * (lane & 3);
            atomicAdd(o0 + h,     o[j][0]);
            atomicAdd(o0 + h + 1, o[j][1]);
            atomicAdd(o1 + h,     o[j][2]);
            atomicAdd(o1 + h + 1, o[j][3]);
        }
    };

    // ---- prologue: K and V as SEPARATE groups ----
    issue_k(b, kb);
    CP_COMMIT();
    issue_v(b, kb);
    CP_COMMIT();
    load_q(b, qi);
    __syncthreads();
    build_q();
    zero_acc();

    for (int it = 0; it < cnt; ++it) {
        // next-tile indices (needed mid-tile for the split issues)
        int nb = b, nqi = qi, nkb = kb + 1;
        bool changed = false;
        if (nkb > (qi >> 1)) {
            nkb = 0; ++nqi; changed = true;
            if (nqi == 64) { nqi = 0; ++nb; }
        }
        const bool last = (it == cnt - 1);

        CP_WAIT1();                        // K_it arrived (pending: K_it, V_it)
        __syncthreads();                   // K visible to all warps

        const int k0 = kb * 128;
        const int ra = qi * 64 + w * 16 + (lane >> 2);
        const bool diag = (kb == (qi >> 1));

        // ---- S = Q K^T (reads K smem) ----
        float s[16][4];
#pragma unroll
        for (int j = 0; j < 16; ++j)
#pragma unroll
            for (int c = 0; c < 4; ++c) s[j][c] = 0.f;
#pragma unroll
        for (int j2 = 0; j2 < 8; ++j2) {
            float* sA = s[2 * j2];
            float* sB = s[2 * j2 + 1];
#pragma unroll
            for (int ks = 0; ks < 4; ++ks) {
                uint32_t kh[4], kl[4];
                uint32_t a = sb + kpat + j2 * (16 * 144) + ks * 32;
                ldsm_x4(kh, a + STG_KHI);
                ldsm_x4(kl, a + STG_KLO);
                mma_bf16(sA, qh[ks], kh[0], kh[1]);
                mma_bf16(sA, qh[ks], kl[0], kl[1]);
                mma_bf16(sA, ql[ks], kh[0], kh[1]);
                mma_bf16(sB, qh[ks], kh[2], kh[3]);
                mma_bf16(sB, qh[ks], kl[2], kl[3]);
                mma_bf16(sB, ql[ks], kh[2], kh[3]);
            }
        }
        __syncthreads();                   // all warps done reading K
        if (!last) { issue_k(nb, nkb); CP_COMMIT(); }   // K_next overlaps exp+PV

        // ---- exp (+ causal mask on diagonal tile) — registers only ----
        if (diag) {
#pragma unroll
            for (int j = 0; j < 16; ++j) {
                int col = k0 + 8 * j + 2 * (lane & 3);
                float e0 = (col     <= ra)     ? __expf(s[j][0]) : 0.f;
                float e1 = (col + 1 <= ra)     ? __expf(s[j][1]) : 0.f;
                float e2 = (col     <= ra + 8) ? __expf(s[j][2]) : 0.f;
                float e3 = (col + 1 <= ra + 8) ? __expf(s[j][3]) : 0.f;
                s[j][0] = e0; s[j][1] = e1; s[j][2] = e2; s[j][3] = e3;
                l0 += e0 + e1; l1 += e2 + e3;
            }
        } else {
#pragma unroll
            for (int j = 0; j < 16; ++j) {
                float e0 = __expf(s[j][0]);
                float e1 = __expf(s[j][1]);
                float e2 = __expf(s[j][2]);
                float e3 = __expf(s[j][3]);
                s[j][0] = e0; s[j][1] = e1; s[j][2] = e2; s[j][3] = e3;
                l0 += e0 + e1; l1 += e2 + e3;
            }
        }

        // pending: {V_it, K_next} (or {V_it} on last tile)
        if (!last) { CP_WAIT1(); } else { CP_WAIT0(); }
        __syncthreads();                   // V visible to all warps

        // ---- O += P V (reads V smem) ----
#pragma unroll
        for (int kc = 0; kc < 8; ++kc) {
            uint32_t ah[4], al[4];
#pragma unroll
            for (int half = 0; half < 2; ++half) {
                const float* sp = s[2 * kc + half];
                float h0 = __bfloat162float(__float2bfloat16(sp[0]));
                float h1 = __bfloat162float(__float2bfloat16(sp[1]));
                float h2 = __bfloat162float(__float2bfloat16(sp[2]));
                float h3 = __bfloat162float(__float2bfloat16(sp[3]));
                ah[2 * half + 0] = pack_bf16x2(sp[0], sp[1]);
                ah[2 * half + 1] = pack_bf16x2(sp[2], sp[3]);
                al[2 * half + 0] = pack_bf16x2(sp[0] - h0, sp[1] - h1);
                al[2 * half + 1] = pack_bf16x2(sp[2] - h2, sp[3] - h3);
            }
#pragma unroll
            for (int jp = 0; jp < 4; ++jp) {
                uint32_t vh[4], vl[4];
                uint32_t a = sb + STG_VHI + vpat + jp * (16 * 272) + kc * 32;
                ldsm_x4(vh, a);
                ldsm_x4(vl, a + (STG_VLO - STG_VHI));
                mma_bf16(o[2 * jp],     ah, vh[0], vh[1]);
                mma_bf16(o[2 * jp],     al, vh[0], vh[1]);
                mma_bf16(o[2 * jp],     ah, vl[0], vl[1]);
                mma_bf16(o[2 * jp + 1], ah, vh[2], vh[3]);
                mma_bf16(o[2 * jp + 1], al, vh[2], vh[3]);
                mma_bf16(o[2 * jp + 1], ah, vl[2], vl[3]);
            }
        }
        __syncthreads();                   // all warps done reading V
        if (!last) { issue_v(nb, nkb); CP_COMMIT(); }   // V_next overlaps next S

        if (!last && changed) {
            flush(b, qi);
            load_q(nb, nqi);
            __syncthreads();
            build_q();
            zero_acc();
        }
        b = nb; qi = nqi; kb = nkb;
    }
    // final flush: recover the indices of the last computed tile
    {
        int pb = b, pqi = qi;
        if (kb == 0) {                     // we just wrapped a q-tile
            if (pqi == 0) { --pb; pqi = 64; }
            --pqi;
        }
        flush(pb, pqi);
    }
}

// ===========================================================================
// Kernel 3: normalize — out = O / l   (one float4 per thread, full chip)
// ===========================================================================
__global__ void norm_kernel(float* __restrict__ out)
{
    const int i = blockIdx.x * 256 + threadIdx.x;       // 262144 = NROWS*NH/4
    float4 v = reinterpret_cast<const float4*>(g_oacc)[i];
    float linv = 1.f / g_lacc[i >> 4];
    v.x *= linv; v.y *= linv; v.z *= linv; v.w *= linv;
    reinterpret_cast<float4*>(out)[i] = v;
}

// ===========================================================================
extern "C" void kernel_launch(void* const* d_in, const int* in_sizes, int n_in,
                              void* d_out, int out_size)
{
    (void)in_sizes; (void)n_in; (void)out_size;
    const float* x  = (const float*)d_in[0];
    const float* Wq = (const float*)d_in[1];
    const float* Wk = (const float*)d_in[2];
    const float* Wv = (const float*)d_in[3];
    float* out = (float*)d_out;

    cudaFuncSetAttribute(qkv_mma, cudaFuncAttributeMaxDynamicSharedMemorySize, QS_TOTAL);
    cudaFuncSetAttribute(attn_mma, cudaFuncAttributeMaxDynamicSharedMemorySize, SM_ATT_TOTAL);

    init_kernel<<<512, 256>>>(Wq, Wk, Wv);
    qkv_mma<<<128, 256, QS_TOTAL>>>(x);
    attn_mma<<<296, 128, SM_ATT_TOTAL>>>();
    norm_kernel<<<1024, 256>>>(out);
}